// round 1
// baseline (speedup 1.0000x reference)
#include <cuda_runtime.h>

#define Bq 8
#define Nq 256
#define Lq 48
#define Fq 96
#define LF (Lq*Fq)

// ---------------- scratch (device globals, no allocation) ----------------
__device__ __align__(16) float g_rowsum[Bq*Nq*Lq];
__device__ __align__(16) float g_colpart[4*Bq*Nq*Lq];   // 4 i-chunks of colsum
__device__ __align__(16) float g_diag[Bq*Nq*Lq];
__device__ __align__(16) float g_trace[Bq*Lq];
__device__ __align__(16) float g_totsum[Bq*Lq];
__device__ __align__(16) float g_bi[Bq*Nq*Fq];          // bi + global scalar folded in
__device__ __align__(16) float g_bj[Bq*Nq*Fq];
__device__ __align__(16) float g_dg[Bq*Nq*Fq];          // diagonal-only term

// ---------------- f32x2 helpers (Blackwell packed fp32) ----------------
__device__ __forceinline__ unsigned long long ffma2(unsigned long long a,
                                                    unsigned long long b,
                                                    unsigned long long c) {
    unsigned long long d;
    asm("fma.rn.f32x2 %0, %1, %2, %3;" : "=l"(d) : "l"(a), "l"(b), "l"(c));
    return d;
}
__device__ __forceinline__ unsigned long long pack2(float v) {
    unsigned long long r;
    asm("mov.b64 %0, {%1, %1};" : "=l"(r) : "f"(v));
    return r;
}

// ---------------- pass 1a: rowsum + diag (block per (b,i)) ----------------
__global__ void k_rowsum(const float* __restrict__ x) {
    int blk = blockIdx.x; int b = blk >> 8, i = blk & 255;
    int tid = threadIdx.x;               // 384 threads
    int l = tid % Lq, ys = tid / Lq;     // ys in [0,8)
    const float* base = x + (((long)b*Nq + i) * Nq) * Lq;
    float acc = 0.f;
    #pragma unroll 4
    for (int s = 0; s < 32; s++) {
        int j = ys * 32 + s;
        acc += base[j*Lq + l];
    }
    __shared__ float sp[8][Lq];
    sp[ys][l] = acc;
    __syncthreads();
    if (tid < Lq) {
        float r = 0.f;
        #pragma unroll
        for (int y = 0; y < 8; y++) r += sp[y][tid];
        g_rowsum[(b*Nq + i)*Lq + tid] = r;
        g_diag[(b*Nq + i)*Lq + tid]   = base[i*Lq + tid];
    }
}

// ---------------- pass 1b: colsum partials (block per (b,jt,ic)) ----------------
// grid = Bq * 32 * 4 : b = blk>>7, jt = (blk>>2)&31, ic = blk&3
__global__ void k_colsum(const float* __restrict__ x) {
    int blk = blockIdx.x;
    int b = blk >> 7, jt = (blk >> 2) & 31, ic = blk & 3;
    int tid = threadIdx.x;               // 384 threads
    int l = tid % Lq, y = tid / Lq;      // y in [0,8)
    int j = jt * 8 + y;
    const float* base = x + ((long)b*Nq*Nq + (long)j) * Lq + (long)ic*64*Nq*Lq;
    float acc = 0.f;
    #pragma unroll 4
    for (int i = 0; i < 64; i++)
        acc += base[(long)i*Nq*Lq + l];
    g_colpart[((ic*Bq + b)*Nq + j)*Lq + l] = acc;
}

// ---------------- pass 1c: trace / totsum ----------------
__global__ void k_trace() {
    int b = blockIdx.x; int l = threadIdx.x;   // 48 threads
    float tr = 0.f, ts = 0.f;
    for (int i = 0; i < Nq; i++) {
        tr += g_diag[(b*Nq + i)*Lq + l];
        ts += g_rowsum[(b*Nq + i)*Lq + l];
    }
    g_trace[b*Lq + l] = tr;
    g_totsum[b*Lq + l] = ts;
}

// ---------------- pass 2: small GEMMs -> bi/bj/dg ----------------
__global__ void k_small(const float* __restrict__ w) {
    int idx = blockIdx.x * blockDim.x + threadIdx.x;   // Bq*Nq*Fq threads
    int f = idx % Fq, row = idx / Fq;
    int b = row >> 8;
    const float* d  = g_diag   + row*Lq;
    const float* r  = g_rowsum + row*Lq;
    const float* c0 = g_colpart + (0*Bq*Nq + row)*Lq;
    const float* c1 = g_colpart + (1*Bq*Nq + row)*Lq;
    const float* c2 = g_colpart + (2*Bq*Nq + row)*Lq;
    const float* c3 = g_colpart + (3*Bq*Nq + row)*Lq;
    const float* tr = g_trace  + b*Lq;
    const float* ts = g_totsum + b*Lq;
    float dgv = 0.f, bjv = 0.f, biv = 0.f;
    #pragma unroll 4
    for (int l = 0; l < Lq; l++) {
        const float* wl = w + l*Fq + f;
        float dv = d[l], rv = r[l];
        float cv = c0[l] + c1[l] + c2[l] + c3[l];
        float tv = tr[l], sv = ts[l];
        dgv += dv*wl[0*LF]  + rv*wl[1*LF]  + cv*wl[2*LF]
             + tv*wl[3*LF]  + sv*wl[4*LF];
        bjv += dv*wl[5*LF]  + rv*wl[6*LF]  + cv*wl[7*LF];
        biv += dv*wl[8*LF]  + rv*wl[9*LF]  + cv*wl[10*LF]
             + tv*wl[13*LF] + sv*wl[14*LF];          // global scalar folded into bi
    }
    g_dg[idx] = dgv; g_bj[idx] = bjv; g_bi[idx] = biv;
}

// ---------------- pass 3: dense mainloop ----------------
// block per (b,i); 512 threads: tid = j*2 + fh; each thread does 48 f's of one (i,j)
__global__ void __launch_bounds__(512) k_main(const float* __restrict__ x,
                                              const float* __restrict__ w,
                                              float* __restrict__ out) {
    __shared__ __align__(16) float s_w12[LF];
    __shared__ __align__(16) float s_w11[LF];
    __shared__ __align__(16) float s_bi[Fq];
    __shared__ __align__(16) float s_dg[Fq];

    int blk = blockIdx.x; int b = blk >> 8, i = blk & 255;
    int tid = threadIdx.x;
    int j = tid >> 1, fh = tid & 1;

    for (int t = tid; t < LF; t += 512) {
        s_w11[t] = w[11*LF + t];
        s_w12[t] = w[12*LF + t];
    }
    {
        int rb = (b*Nq + i)*Fq;
        if (tid < Fq)            s_bi[tid]        = g_bi[rb + tid];
        else if (tid < 2*Fq)     s_dg[tid - Fq]   = g_dg[rb + tid - Fq];
    }
    __syncthreads();

    const float4* xa4 = reinterpret_cast<const float4*>(x + (((long)b*Nq + i)*Nq + j)*Lq);
    const float4* xb4 = reinterpret_cast<const float4*>(x + (((long)b*Nq + j)*Nq + i)*Lq);
    const ulonglong2* w12v = reinterpret_cast<const ulonglong2*>(s_w12) + fh*12;
    const ulonglong2* w11v = reinterpret_cast<const ulonglong2*>(s_w11) + fh*12;

    unsigned long long acc[24];
    #pragma unroll
    for (int q = 0; q < 24; q++) acc[q] = 0ull;

    for (int l4 = 0; l4 < 12; l4++) {
        float4 av = xa4[l4];
        float4 bv = xb4[l4];
        #pragma unroll
        for (int k = 0; k < 4; k++) {
            int l = l4*4 + k;
            float afl = (k==0) ? av.x : (k==1) ? av.y : (k==2) ? av.z : av.w;
            float bfl = (k==0) ? bv.x : (k==1) ? bv.y : (k==2) ? bv.z : bv.w;
            unsigned long long xa2 = pack2(afl);
            unsigned long long xb2 = pack2(bfl);
            const ulonglong2* wa = w12v + l*24;
            const ulonglong2* wb = w11v + l*24;
            #pragma unroll
            for (int q = 0; q < 12; q++) {
                ulonglong2 va = wa[q];
                acc[2*q]   = ffma2(xa2, va.x, acc[2*q]);
                acc[2*q+1] = ffma2(xa2, va.y, acc[2*q+1]);
            }
            #pragma unroll
            for (int q = 0; q < 12; q++) {
                ulonglong2 vb = wb[q];
                acc[2*q]   = ffma2(xb2, vb.x, acc[2*q]);
                acc[2*q+1] = ffma2(xb2, vb.y, acc[2*q+1]);
            }
        }
    }

    int f0 = fh * 48;
    const float4* bj4 = reinterpret_cast<const float4*>(g_bj + (b*Nq + j)*Fq + f0);
    float* orow = out + ((((long)b*Nq + i)*Nq + j)*Fq) + f0;
    bool isd = (i == j);
    #pragma unroll
    for (int q = 0; q < 12; q++) {
        float2 a  = *reinterpret_cast<float2*>(&acc[2*q]);
        float2 bb = *reinterpret_cast<float2*>(&acc[2*q+1]);
        float4 bjv = bj4[q];
        int f = 4*q;
        float4 o;
        o.x = a.x  + s_bi[f0+f]   + bjv.x;
        o.y = a.y  + s_bi[f0+f+1] + bjv.y;
        o.z = bb.x + s_bi[f0+f+2] + bjv.z;
        o.w = bb.y + s_bi[f0+f+3] + bjv.w;
        if (isd) {
            o.x += s_dg[f0+f];   o.y += s_dg[f0+f+1];
            o.z += s_dg[f0+f+2]; o.w += s_dg[f0+f+3];
        }
        *reinterpret_cast<float4*>(orow + f) = o;
    }
}

// ---------------- launch ----------------
extern "C" void kernel_launch(void* const* d_in, const int* in_sizes, int n_in,
                              void* d_out, int out_size) {
    const float* x = (const float*)d_in[0];
    const float* w = (const float*)d_in[1];
    if (n_in >= 2 && in_sizes[0] == 15*Lq*Fq) {   // defensive: swap if order reversed
        x = (const float*)d_in[1];
        w = (const float*)d_in[0];
    }
    float* out = (float*)d_out;

    k_rowsum<<<Bq*Nq, 384>>>(x);
    k_colsum<<<Bq*32*4, 384>>>(x);
    k_trace<<<Bq, Lq>>>();
    k_small<<<(Bq*Nq*Fq)/256, 256>>>(w);
    k_main<<<Bq*Nq, 512>>>(x, w, out);
}

// round 3
// speedup vs baseline: 1.3809x; 1.3809x over previous
#include <cuda_runtime.h>
#include <cstdint>

#define Bq 8
#define Nq 256
#define Lq 48
#define Fq 96
#define LF (Lq*Fq)

#if defined(__CUDA_ARCH__) && (__CUDA_ARCH__ == 1030) && \
    (defined(__CUDA_ARCH_FEAT_SM103_ALL) || defined(__CUDA_ARCH_SPECIFIC__) || defined(__CUDA_ARCH_FAMILY_SPECIFIC__))
#define HAS_TCGEN05 1
#else
#define HAS_TCGEN05 0
#endif

// ---------------- scratch ----------------
__device__ __align__(16) float g_rowsum[Bq*Nq*Lq];
__device__ __align__(16) float g_colsum[Bq*Nq*Lq];
__device__ __align__(16) float g_diag[Bq*Nq*Lq];
__device__ __align__(16) float g_dgc[Bq*Fq];
__device__ __align__(16) float g_bic[Bq*Fq];
__device__ __align__(16) float g_bi[Bq*Nq*Fq];
__device__ __align__(16) float g_bj[Bq*Nq*Fq];
__device__ __align__(16) float g_dg[Bq*Nq*Fq];

// ---------------- generic helpers (legal on all sm_10x) ----------------
__device__ __forceinline__ unsigned long long ffma2(unsigned long long a,
                                                    unsigned long long b,
                                                    unsigned long long c) {
    unsigned long long d;
    asm("fma.rn.f32x2 %0, %1, %2, %3;" : "=l"(d) : "l"(a), "l"(b), "l"(c));
    return d;
}
__device__ __forceinline__ unsigned long long pack2(float v) {
    unsigned long long r;
    asm("mov.b64 %0, {%1, %1};" : "=l"(r) : "f"(v));
    return r;
}

// ---------------- pass 1a: rowsum + diag ----------------
__global__ void k_rowsum(const float* __restrict__ x) {
    int blk = blockIdx.x; int b = blk >> 8, i = blk & 255;
    int tid = threadIdx.x;               // 384
    int l = tid % Lq, ys = tid / Lq;
    const float* base = x + (((long)b*Nq + i) * Nq) * Lq;
    float acc = 0.f;
    #pragma unroll 4
    for (int s = 0; s < 32; s++) acc += base[(ys*32 + s)*Lq + l];
    __shared__ float sp[8][Lq];
    sp[ys][l] = acc;
    __syncthreads();
    if (tid < Lq) {
        float r = 0.f;
        #pragma unroll
        for (int y = 0; y < 8; y++) r += sp[y][tid];
        g_rowsum[(b*Nq + i)*Lq + tid] = r;
        g_diag[(b*Nq + i)*Lq + tid]   = base[i*Lq + tid];
    }
}

// ---------------- pass 1b: colsum ----------------
__global__ void k_colsum(const float* __restrict__ x) {
    int blk = blockIdx.x; int b = blk >> 5, jt = blk & 31;
    int tid = threadIdx.x;               // 384
    int l = tid % Lq, y = tid / Lq;
    int j = jt * 8 + y;
    const float* base = x + ((long)b*Nq*Nq + (long)j) * Lq + l;
    float acc = 0.f;
    #pragma unroll 8
    for (int i = 0; i < Nq; i++) acc += base[(long)i * Nq * Lq];
    g_colsum[(b*Nq + j)*Lq + l] = acc;
}

// ---------------- pass 1c: trace/totsum -> per-b F constants ----------------
__global__ void k_trace(const float* __restrict__ w) {
    int b = blockIdx.x; int t = threadIdx.x;   // 96 threads
    __shared__ float s_tr[Lq], s_ts[Lq];
    if (t < Lq) {
        float a = 0.f;
        #pragma unroll 8
        for (int i = 0; i < Nq; i++) a += g_diag[(b*Nq + i)*Lq + t];
        s_tr[t] = a;
    } else {
        int l = t - Lq;
        float a = 0.f;
        #pragma unroll 8
        for (int i = 0; i < Nq; i++) a += g_rowsum[(b*Nq + i)*Lq + l];
        s_ts[l] = a;
    }
    __syncthreads();
    float dgc = 0.f, bic = 0.f;
    #pragma unroll 4
    for (int l = 0; l < Lq; l++) {
        float tr = s_tr[l], ts = s_ts[l];
        dgc += tr * w[3*LF  + l*Fq + t] + ts * w[4*LF  + l*Fq + t];
        bic += tr * w[13*LF + l*Fq + t] + ts * w[14*LF + l*Fq + t];
    }
    g_dgc[b*Fq + t] = dgc;
    g_bic[b*Fq + t] = bic;
}

// ---------------- pass 2: small GEMMs -> bi/bj/dg ----------------
__global__ void __launch_bounds__(384) k_small(const float* __restrict__ w) {
    __shared__ float sd[16][Lq], sr[16][Lq], sc[16][Lq];
    int row0 = blockIdx.x * 16;
    int tid = threadIdx.x;
    for (int idx = tid; idx < 16*Lq; idx += 384) {
        int r = idx / Lq, l = idx % Lq;
        sd[r][l] = g_diag  [(row0 + r)*Lq + l];
        sr[r][l] = g_rowsum[(row0 + r)*Lq + l];
        sc[r][l] = g_colsum[(row0 + r)*Lq + l];
    }
    __syncthreads();
    int fx = tid % 24, y = tid / 24;
    int row = row0 + y; int b = row >> 8;
    float4 dg = {0,0,0,0}, bj = {0,0,0,0}, bi = {0,0,0,0};
    const float4* w4 = (const float4*)w;
    #pragma unroll 4
    for (int l = 0; l < Lq; l++) {
        float dv = sd[y][l], rv = sr[y][l], cv = sc[y][l];
        int base = (l*Fq)/4 + fx;
        float4 w0 = w4[base + (0*LF)/4],  w1 = w4[base + (1*LF)/4],  w2 = w4[base + (2*LF)/4];
        float4 w5 = w4[base + (5*LF)/4],  w6 = w4[base + (6*LF)/4],  w7 = w4[base + (7*LF)/4];
        float4 w8 = w4[base + (8*LF)/4],  w9 = w4[base + (9*LF)/4],  wA = w4[base + (10*LF)/4];
        dg.x += dv*w0.x + rv*w1.x + cv*w2.x;  dg.y += dv*w0.y + rv*w1.y + cv*w2.y;
        dg.z += dv*w0.z + rv*w1.z + cv*w2.z;  dg.w += dv*w0.w + rv*w1.w + cv*w2.w;
        bj.x += dv*w5.x + rv*w6.x + cv*w7.x;  bj.y += dv*w5.y + rv*w6.y + cv*w7.y;
        bj.z += dv*w5.z + rv*w6.z + cv*w7.z;  bj.w += dv*w5.w + rv*w6.w + cv*w7.w;
        bi.x += dv*w8.x + rv*w9.x + cv*wA.x;  bi.y += dv*w8.y + rv*w9.y + cv*wA.y;
        bi.z += dv*w8.z + rv*w9.z + cv*wA.z;  bi.w += dv*w8.w + rv*w9.w + cv*wA.w;
    }
    int f = fx * 4;
    const float4 dgc = *(const float4*)(g_dgc + b*Fq + f);
    const float4 bic = *(const float4*)(g_bic + b*Fq + f);
    dg.x += dgc.x; dg.y += dgc.y; dg.z += dgc.z; dg.w += dgc.w;
    bi.x += bic.x; bi.y += bic.y; bi.z += bic.z; bi.w += bic.w;
    *(float4*)(g_dg + row*Fq + f) = dg;
    *(float4*)(g_bj + row*Fq + f) = bj;
    *(float4*)(g_bi + row*Fq + f) = bi;
}

// ============================================================================
// tcgen05 path (sm_103a only)
// ============================================================================
#if HAS_TCGEN05
__device__ __forceinline__ uint32_t smem_u32(const void* p) {
    uint32_t a;
    asm("{ .reg .u64 t; cvta.to.shared.u64 t, %1; cvt.u32.u64 %0, t; }" : "=r"(a) : "l"(p));
    return a;
}
__device__ __forceinline__ uint32_t elect_one() {
    uint32_t p;
    asm volatile("{\n\t.reg .pred p;\n\telect.sync _|p, 0xFFFFFFFF;\n\tselp.b32 %0, 1, 0, p;\n\t}" : "=r"(p));
    return p;
}
__device__ __forceinline__ float tf32_rna(float x) {
    uint32_t r;
    asm("cvt.rna.tf32.f32 %0, %1;" : "=r"(r) : "f"(x));
    return __uint_as_float(r);
}
__device__ __forceinline__ void mma_tf32_ss(uint32_t d, uint64_t ad, uint64_t bd,
                                            uint32_t idesc, uint32_t en) {
    asm volatile(
        "{\n\t.reg .pred p;\n\tsetp.ne.u32 p, %4, 0;\n\t"
        "tcgen05.mma.cta_group::1.kind::tf32 [%0], %1, %2, %3, {%5, %5, %5, %5}, p;\n\t}"
        :: "r"(d), "l"(ad), "l"(bd), "r"(idesc), "r"(en), "r"(0u) : "memory");
}
#define TC_ALLOC(sm, n)   asm volatile("tcgen05.alloc.cta_group::1.sync.aligned.shared::cta.b32 [%0], %1;" :: "r"(sm), "r"(n) : "memory")
#define TC_DEALLOC(t, n)  asm volatile("tcgen05.dealloc.cta_group::1.sync.aligned.b32 %0, %1;" :: "r"(t), "r"(n))
#define TC_RELINQ()       asm volatile("tcgen05.relinquish_alloc_permit.cta_group::1.sync.aligned;")
#define TC_COMMIT(mb)     asm volatile("tcgen05.commit.cta_group::1.mbarrier::arrive::one.shared::cluster.b64 [%0];" :: "r"(mb) : "memory")
#define TC_WAIT_LD()      asm volatile("tcgen05.wait::ld.sync.aligned;" ::: "memory")
#define TC_FENCE_BEFORE() asm volatile("tcgen05.fence::before_thread_sync;" ::: "memory")
#define TC_FENCE_AFTER()  asm volatile("tcgen05.fence::after_thread_sync;" ::: "memory")
#define FENCE_ASYNC()     asm volatile("fence.proxy.async.shared::cta;" ::: "memory")
#define MBAR_INIT(mb, c)  asm volatile("mbarrier.init.shared.b64 [%0], %1;" :: "r"(mb), "r"(c) : "memory")
#define MBAR_INVAL(mb)    asm volatile("mbarrier.inval.shared.b64 [%0];" :: "r"(mb) : "memory")
__device__ __forceinline__ void mbar_wait(uint32_t mb, uint32_t ph) {
    uint32_t done;
    asm volatile(
        "{\n\t.reg .pred p;\n\t"
        "mbarrier.try_wait.parity.acquire.cta.shared::cta.b64 p, [%1], %2;\n\t"
        "selp.b32 %0, 1, 0, p;\n\t}"
        : "=r"(done) : "r"(mb), "r"(ph) : "memory");
    if (!done) {
        asm volatile(
            "{\n\t.reg .pred P1;\n\t"
            "WL_%=:\n\t"
            "mbarrier.try_wait.parity.acquire.cta.shared::cta.b64 P1, [%0], %1, 0x989680;\n\t"
            "@P1 bra.uni WD_%=;\n\t"
            "bra.uni WL_%=;\n\t"
            "WD_%=:\n\t}"
            :: "r"(mb), "r"(ph) : "memory");
    }
}
#define LDTM_X32(r, a) \
    asm volatile("tcgen05.ld.sync.aligned.32x32b.x32.b32 " \
        "{%0, %1, %2, %3, %4, %5, %6, %7, %8, %9, %10, %11, %12, %13, %14, %15, " \
        " %16, %17, %18, %19, %20, %21, %22, %23, %24, %25, %26, %27, %28, %29, %30, %31}, [%32];" \
        : "=r"((r)[0]),  "=r"((r)[1]),  "=r"((r)[2]),  "=r"((r)[3]), \
          "=r"((r)[4]),  "=r"((r)[5]),  "=r"((r)[6]),  "=r"((r)[7]), \
          "=r"((r)[8]),  "=r"((r)[9]),  "=r"((r)[10]), "=r"((r)[11]), \
          "=r"((r)[12]), "=r"((r)[13]), "=r"((r)[14]), "=r"((r)[15]), \
          "=r"((r)[16]), "=r"((r)[17]), "=r"((r)[18]), "=r"((r)[19]), \
          "=r"((r)[20]), "=r"((r)[21]), "=r"((r)[22]), "=r"((r)[23]), \
          "=r"((r)[24]), "=r"((r)[25]), "=r"((r)[26]), "=r"((r)[27]), \
          "=r"((r)[28]), "=r"((r)[29]), "=r"((r)[30]), "=r"((r)[31]) \
        : "r"(a))

static constexpr uint64_t DESC_BASE_SW128 =
    (uint64_t(2) << 61) | (uint64_t(1) << 46) | (uint64_t(64) << 32) | (uint64_t(1) << 16);
#define MK_DESC(addr) (DESC_BASE_SW128 | ((uint64_t)((addr) >> 4) & 0x3FFF))
#define IDESC_TF32 ((1u<<4) | (2u<<7) | (2u<<10) | (12u<<17) | (8u<<24))

__device__ __forceinline__ uint32_t a_off(int row, int f) {
    uint32_t o = ((f >> 5) * 16384u) + (uint32_t)row * 128u + ((f & 31) << 2);
    return o ^ ((o >> 3) & 0x70u);
}
__device__ __forceinline__ uint32_t b_off(int n, int k) {
    uint32_t o = ((k >> 5) * 12288u) + (uint32_t)n * 128u + ((k & 31) << 2);
    return o ^ ((o >> 3) & 0x70u);
}
__device__ __forceinline__ uint64_t acd(int c) { return (uint64_t)((c >> 2) * 1024 + (c & 3) * 2); }
__device__ __forceinline__ uint64_t bcd(int c) { return (uint64_t)((c >> 2) * 768  + (c & 3) * 2); }
#endif // HAS_TCGEN05

#define OFF_TMEM 0
#define OFF_MBAR 16
#define OFF_BI   32
#define OFF_DG   (32 + 384)
#define OFF_B12  1024
#define OFF_B11  (OFF_B12 + 36864)
#define OFF_AS   (OFF_B11 + 36864)
#define OFF_AT   (OFF_AS + 49152)
#define SMEM_TOT (OFF_AT + 49152)

// grid 128: b = blk>>4, jt = (blk>>3)&1, ic = blk&7; 32 i-iters per block.
__global__ void __launch_bounds__(256, 1) k_mma(const float* __restrict__ x,
                                                const float* __restrict__ w,
                                                float* __restrict__ out) {
#if HAS_TCGEN05
    extern __shared__ char sm[];
    uint32_t smb = smem_u32(sm);
    int tid = threadIdx.x;
    int wid = tid >> 5, lane = tid & 31;

    int blk = blockIdx.x;
    int b = blk >> 4, jt = (blk >> 3) & 1, ic = blk & 7;
    int j0 = jt * 128;

    if (wid == 0) TC_ALLOC(smb + OFF_TMEM, 128);
    __syncthreads();
    uint32_t tmem;
    asm volatile("ld.shared.b32 %0, [%1];" : "=r"(tmem) : "r"(smb + OFF_TMEM));

    if (tid == 0) MBAR_INIT(smb + OFF_MBAR, 1);

    // B tiles: W12/W11 transposed into [f rows, k cols], 3xTF32 split
    for (int idx = tid; idx < Lq*Fq; idx += 256) {
        int f = idx / Lq, l = idx % Lq;
        float v12 = w[12*LF + l*Fq + f];
        float v11 = w[11*LF + l*Fq + f];
        float h12 = tf32_rna(v12), h11 = tf32_rna(v11);
        *(float*)(sm + OFF_B12 + b_off(f, l))      = h12;
        *(float*)(sm + OFF_B12 + b_off(f, l + Lq)) = v12 - h12;
        *(float*)(sm + OFF_B11 + b_off(f, l))      = h11;
        *(float*)(sm + OFF_B11 + b_off(f, l + Lq)) = v11 - h11;
    }
    FENCE_ASYNC();
    __syncthreads();

    uint64_t dAs  = MK_DESC(smb + OFF_AS);
    uint64_t dAt  = MK_DESC(smb + OFF_AT);
    uint64_t dB12 = MK_DESC(smb + OFF_B12);
    uint64_t dB11 = MK_DESC(smb + OFF_B11);

    uint32_t phase = 0;

    for (int it = 0; it < 32; it++) {
        int i = ic * 32 + it;
        __syncthreads();

        const float4* xs = (const float4*)(x + (((long)b*Nq + i)*Nq + j0)*Lq);
        #pragma unroll
        for (int q = 0; q < 6; q++) {
            int idx4 = tid + 256*q;
            int r = idx4 / 12, l4 = idx4 % 12;
            float4 v = xs[idx4];
            float4 h, lo;
            h.x = tf32_rna(v.x); lo.x = v.x - h.x;
            h.y = tf32_rna(v.y); lo.y = v.y - h.y;
            h.z = tf32_rna(v.z); lo.z = v.z - h.z;
            h.w = tf32_rna(v.w); lo.w = v.w - h.w;
            int lb = l4 * 4;
            *(float4*)(sm + OFF_AS + a_off(r, lb))      = h;
            *(float4*)(sm + OFF_AS + a_off(r, lb + Lq)) = lo;
        }
        const float* xt0 = x + ((long)b*Nq + j0)*Nq*Lq + (long)i*Lq;
        #pragma unroll
        for (int q = 0; q < 6; q++) {
            int idx4 = tid + 256*q;
            int r = idx4 / 12, l4 = idx4 % 12;
            float4 v = *(const float4*)(xt0 + (long)r*Nq*Lq + l4*4);
            float4 h, lo;
            h.x = tf32_rna(v.x); lo.x = v.x - h.x;
            h.y = tf32_rna(v.y); lo.y = v.y - h.y;
            h.z = tf32_rna(v.z); lo.z = v.z - h.z;
            h.w = tf32_rna(v.w); lo.w = v.w - h.w;
            int lb = l4 * 4;
            *(float4*)(sm + OFF_AT + a_off(r, lb))      = h;
            *(float4*)(sm + OFF_AT + a_off(r, lb + Lq)) = lo;
        }
        if (tid < Fq)            ((float*)(sm + OFF_BI))[tid]       = g_bi[(b*Nq + i)*Fq + tid];
        else if (tid < 2*Fq)     ((float*)(sm + OFF_DG))[tid - Fq]  = g_dg[(b*Nq + i)*Fq + tid - Fq];

        FENCE_ASYNC();
        __syncthreads();

        if (wid == 4 && elect_one()) {
            TC_FENCE_AFTER();
            uint32_t en = 0;
            #pragma unroll
            for (int c = 0; c < 6; c++) { mma_tf32_ss(tmem, dAs + acd(c),     dB12 + bcd(c),     IDESC_TF32, en); en = 1; }
            #pragma unroll
            for (int c = 0; c < 6; c++)   mma_tf32_ss(tmem, dAs + acd(c + 6), dB12 + bcd(c),     IDESC_TF32, 1);
            #pragma unroll
            for (int c = 0; c < 6; c++)   mma_tf32_ss(tmem, dAs + acd(c),     dB12 + bcd(c + 6), IDESC_TF32, 1);
            #pragma unroll
            for (int c = 0; c < 6; c++)   mma_tf32_ss(tmem, dAt + acd(c),     dB11 + bcd(c),     IDESC_TF32, 1);
            #pragma unroll
            for (int c = 0; c < 6; c++)   mma_tf32_ss(tmem, dAt + acd(c + 6), dB11 + bcd(c),     IDESC_TF32, 1);
            #pragma unroll
            for (int c = 0; c < 6; c++)   mma_tf32_ss(tmem, dAt + acd(c),     dB11 + bcd(c + 6), IDESC_TF32, 1);
            TC_COMMIT(smb + OFF_MBAR);
        }

        mbar_wait(smb + OFF_MBAR, phase);
        phase ^= 1;
        TC_FENCE_AFTER();

        if (tid < 128) {
            uint32_t d[96];
            LDTM_X32(d,      tmem);
            LDTM_X32(d + 32, tmem + 32);
            LDTM_X32(d + 64, tmem + 64);
            TC_WAIT_LD();
            int row = wid * 32 + lane;
            int j = j0 + row;
            const float4* bj4 = (const float4*)(g_bj + ((long)b*Nq + j)*Fq);
            const float4* bi4 = (const float4*)(sm + OFF_BI);
            const float4* dg4 = (const float4*)(sm + OFF_DG);
            float4* op = (float4*)(out + (((long)b*Nq + i)*Nq + j)*Fq);
            bool isd = (j == i);
            #pragma unroll
            for (int q = 0; q < 24; q++) {
                float4 bv = bj4[q], iv = bi4[q];
                float4 o;
                o.x = __uint_as_float(d[4*q+0]) + iv.x + bv.x;
                o.y = __uint_as_float(d[4*q+1]) + iv.y + bv.y;
                o.z = __uint_as_float(d[4*q+2]) + iv.z + bv.z;
                o.w = __uint_as_float(d[4*q+3]) + iv.w + bv.w;
                if (isd) {
                    float4 gv = dg4[q];
                    o.x += gv.x; o.y += gv.y; o.z += gv.z; o.w += gv.w;
                }
                op[q] = o;
            }
            TC_FENCE_BEFORE();
        }
    }

    __syncthreads();
    if (tid == 0) MBAR_INVAL(smb + OFF_MBAR);
    __syncthreads();
    if (wid == 0) {
        TC_RELINQ();
        TC_DEALLOC(tmem, 128);
    }
#endif // HAS_TCGEN05
}

// ============================================================================
// CUDA-core fallback dense kernel (active only when tcgen05 is unavailable)
// ============================================================================
__global__ void __launch_bounds__(512) k_main_fb(const float* __restrict__ x,
                                                 const float* __restrict__ w,
                                                 float* __restrict__ out) {
#if !HAS_TCGEN05
    __shared__ __align__(16) float s_w12[LF];
    __shared__ __align__(16) float s_w11[LF];
    __shared__ __align__(16) float s_bi[Fq];
    __shared__ __align__(16) float s_dg[Fq];

    int blk = blockIdx.x; int b = blk >> 8, i = blk & 255;
    int tid = threadIdx.x;
    int j = tid >> 1, fh = tid & 1;

    for (int t = tid; t < LF; t += 512) {
        s_w11[t] = w[11*LF + t];
        s_w12[t] = w[12*LF + t];
    }
    {
        int rb = (b*Nq + i)*Fq;
        if (tid < Fq)            s_bi[tid]        = g_bi[rb + tid];
        else if (tid < 2*Fq)     s_dg[tid - Fq]   = g_dg[rb + tid - Fq];
    }
    __syncthreads();

    const float4* xa4 = (const float4*)(x + (((long)b*Nq + i)*Nq + j)*Lq);
    const float4* xb4 = (const float4*)(x + (((long)b*Nq + j)*Nq + i)*Lq);
    const ulonglong2* w12v = ((const ulonglong2*)s_w12) + fh*12;
    const ulonglong2* w11v = ((const ulonglong2*)s_w11) + fh*12;

    unsigned long long acc[24];
    #pragma unroll
    for (int q = 0; q < 24; q++) acc[q] = 0ull;

    for (int l4 = 0; l4 < 12; l4++) {
        float4 av = xa4[l4];
        float4 bv = xb4[l4];
        #pragma unroll
        for (int k = 0; k < 4; k++) {
            int l = l4*4 + k;
            float afl = (k==0) ? av.x : (k==1) ? av.y : (k==2) ? av.z : av.w;
            float bfl = (k==0) ? bv.x : (k==1) ? bv.y : (k==2) ? bv.z : bv.w;
            unsigned long long xa2 = pack2(afl);
            unsigned long long xb2 = pack2(bfl);
            const ulonglong2* wa = w12v + l*24;
            const ulonglong2* wb = w11v + l*24;
            #pragma unroll
            for (int q = 0; q < 12; q++) {
                ulonglong2 va = wa[q];
                acc[2*q]   = ffma2(xa2, va.x, acc[2*q]);
                acc[2*q+1] = ffma2(xa2, va.y, acc[2*q+1]);
            }
            #pragma unroll
            for (int q = 0; q < 12; q++) {
                ulonglong2 vb = wb[q];
                acc[2*q]   = ffma2(xb2, vb.x, acc[2*q]);
                acc[2*q+1] = ffma2(xb2, vb.y, acc[2*q+1]);
            }
        }
    }

    int f0 = fh * 48;
    const float4* bj4 = (const float4*)(g_bj + (b*Nq + j)*Fq + f0);
    float* orow = out + ((((long)b*Nq + i)*Nq + j)*Fq) + f0;
    bool isd = (i == j);
    #pragma unroll
    for (int q = 0; q < 12; q++) {
        float2 a  = *(float2*)(&acc[2*q]);
        float2 bb = *(float2*)(&acc[2*q+1]);
        float4 bjv = bj4[q];
        int f = 4*q;
        float4 o;
        o.x = a.x  + s_bi[f0+f]   + bjv.x;
        o.y = a.y  + s_bi[f0+f+1] + bjv.y;
        o.z = bb.x + s_bi[f0+f+2] + bjv.z;
        o.w = bb.y + s_bi[f0+f+3] + bjv.w;
        if (isd) {
            o.x += s_dg[f0+f];   o.y += s_dg[f0+f+1];
            o.z += s_dg[f0+f+2]; o.w += s_dg[f0+f+3];
        }
        *(float4*)(orow + f) = o;
    }
#endif // !HAS_TCGEN05
}

// ---------------- launch ----------------
extern "C" void kernel_launch(void* const* d_in, const int* in_sizes, int n_in,
                              void* d_out, int out_size) {
    const float* x = (const float*)d_in[0];
    const float* w = (const float*)d_in[1];
    if (n_in >= 2 && in_sizes[0] == 15*Lq*Fq) {
        x = (const float*)d_in[1];
        w = (const float*)d_in[0];
    }
    float* out = (float*)d_out;

    cudaFuncSetAttribute(k_mma, cudaFuncAttributeMaxDynamicSharedMemorySize, SMEM_TOT);

    k_rowsum<<<Bq*Nq, 384>>>(x);
    k_colsum<<<Bq*32, 384>>>(x);
    k_trace<<<Bq, 2*Lq>>>(w);
    k_small<<<128, 384>>>(w);
    k_mma<<<128, 256, SMEM_TOT>>>(x, w, out);       // does the work iff tcgen05 available
    k_main_fb<<<Bq*Nq*Nq/Nq, 512>>>(x, w, out);     // 2048 blocks; work iff NOT available
}

// round 4
// speedup vs baseline: 1.4373x; 1.0408x over previous
#include <cuda_runtime.h>
#include <cstdint>

#define Bq 8
#define Nq 256
#define Lq 48
#define Fq 96
#define LF (Lq*Fq)

#if defined(__CUDA_ARCH__) && (__CUDA_ARCH__ == 1030) && \
    (defined(__CUDA_ARCH_FEAT_SM103_ALL) || defined(__CUDA_ARCH_SPECIFIC__) || defined(__CUDA_ARCH_FAMILY_SPECIFIC__))
#define HAS_TCGEN05 1
#else
#define HAS_TCGEN05 0
#endif

// ---------------- scratch ----------------
__device__ __align__(16) float g_rowsum[Bq*Nq*Lq];
__device__ __align__(16) float g_colsum[Bq*Nq*Lq];
__device__ __align__(16) float g_diag[Bq*Nq*Lq];
__device__ __align__(16) float g_dgc[Bq*Fq];
__device__ __align__(16) float g_bic[Bq*Fq];
__device__ __align__(16) float g_bi[Bq*Nq*Fq];
__device__ __align__(16) float g_bj[Bq*Nq*Fq];
__device__ __align__(16) float g_dg[Bq*Nq*Fq];

// ---------------- generic helpers ----------------
__device__ __forceinline__ unsigned long long ffma2(unsigned long long a,
                                                    unsigned long long b,
                                                    unsigned long long c) {
    unsigned long long d;
    asm("fma.rn.f32x2 %0, %1, %2, %3;" : "=l"(d) : "l"(a), "l"(b), "l"(c));
    return d;
}
__device__ __forceinline__ unsigned long long pack2(float v) {
    unsigned long long r;
    asm("mov.b64 %0, {%1, %1};" : "=l"(r) : "f"(v));
    return r;
}

// ---------------- pass 1a: rowsum + diag ----------------
__global__ void k_rowsum(const float* __restrict__ x) {
    int blk = blockIdx.x; int b = blk >> 8, i = blk & 255;
    int tid = threadIdx.x;               // 384
    int l = tid % Lq, ys = tid / Lq;
    const float* base = x + (((long)b*Nq + i) * Nq) * Lq;
    float acc = 0.f;
    #pragma unroll 4
    for (int s = 0; s < 32; s++) acc += base[(ys*32 + s)*Lq + l];
    __shared__ float sp[8][Lq];
    sp[ys][l] = acc;
    __syncthreads();
    if (tid < Lq) {
        float r = 0.f;
        #pragma unroll
        for (int y = 0; y < 8; y++) r += sp[y][tid];
        g_rowsum[(b*Nq + i)*Lq + tid] = r;
        g_diag[(b*Nq + i)*Lq + tid]   = base[i*Lq + tid];
    }
}

// ---------------- pass 1b: colsum ----------------
__global__ void k_colsum(const float* __restrict__ x) {
    int blk = blockIdx.x; int b = blk >> 5, jt = blk & 31;
    int tid = threadIdx.x;               // 384
    int l = tid % Lq, y = tid / Lq;
    int j = jt * 8 + y;
    const float* base = x + ((long)b*Nq*Nq + (long)j) * Lq + l;
    float acc = 0.f;
    #pragma unroll 8
    for (int i = 0; i < Nq; i++) acc += base[(long)i * Nq * Lq];
    g_colsum[(b*Nq + j)*Lq + l] = acc;
}

// ---------------- pass 1c: trace/totsum -> per-b F constants ----------------
__global__ void k_trace(const float* __restrict__ w) {
    int b = blockIdx.x; int t = threadIdx.x;   // 96 threads
    __shared__ float s_tr[Lq], s_ts[Lq];
    if (t < Lq) {
        float a = 0.f;
        #pragma unroll 8
        for (int i = 0; i < Nq; i++) a += g_diag[(b*Nq + i)*Lq + t];
        s_tr[t] = a;
    } else {
        int l = t - Lq;
        float a = 0.f;
        #pragma unroll 8
        for (int i = 0; i < Nq; i++) a += g_rowsum[(b*Nq + i)*Lq + l];
        s_ts[l] = a;
    }
    __syncthreads();
    float dgc = 0.f, bic = 0.f;
    #pragma unroll 4
    for (int l = 0; l < Lq; l++) {
        float tr = s_tr[l], ts = s_ts[l];
        dgc += tr * w[3*LF  + l*Fq + t] + ts * w[4*LF  + l*Fq + t];
        bic += tr * w[13*LF + l*Fq + t] + ts * w[14*LF + l*Fq + t];
    }
    g_dgc[b*Fq + t] = dgc;
    g_bic[b*Fq + t] = bic;
}

// ---------------- pass 2: small GEMMs -> bi/bj/dg ----------------
__global__ void __launch_bounds__(384) k_small(const float* __restrict__ w) {
    __shared__ float sd[16][Lq], sr[16][Lq], sc[16][Lq];
    int row0 = blockIdx.x * 16;
    int tid = threadIdx.x;
    for (int idx = tid; idx < 16*Lq; idx += 384) {
        int r = idx / Lq, l = idx % Lq;
        sd[r][l] = g_diag  [(row0 + r)*Lq + l];
        sr[r][l] = g_rowsum[(row0 + r)*Lq + l];
        sc[r][l] = g_colsum[(row0 + r)*Lq + l];
    }
    __syncthreads();
    int fx = tid % 24, y = tid / 24;
    int row = row0 + y; int b = row >> 8;
    float4 dg = {0,0,0,0}, bj = {0,0,0,0}, bi = {0,0,0,0};
    const float4* w4 = (const float4*)w;
    #pragma unroll 8
    for (int l = 0; l < Lq; l++) {
        float dv = sd[y][l], rv = sr[y][l], cv = sc[y][l];
        int base = (l*Fq)/4 + fx;
        float4 w0 = w4[base + (0*LF)/4],  w1 = w4[base + (1*LF)/4],  w2 = w4[base + (2*LF)/4];
        float4 w5 = w4[base + (5*LF)/4],  w6 = w4[base + (6*LF)/4],  w7 = w4[base + (7*LF)/4];
        float4 w8 = w4[base + (8*LF)/4],  w9 = w4[base + (9*LF)/4],  wA = w4[base + (10*LF)/4];
        dg.x += dv*w0.x + rv*w1.x + cv*w2.x;  dg.y += dv*w0.y + rv*w1.y + cv*w2.y;
        dg.z += dv*w0.z + rv*w1.z + cv*w2.z;  dg.w += dv*w0.w + rv*w1.w + cv*w2.w;
        bj.x += dv*w5.x + rv*w6.x + cv*w7.x;  bj.y += dv*w5.y + rv*w6.y + cv*w7.y;
        bj.z += dv*w5.z + rv*w6.z + cv*w7.z;  bj.w += dv*w5.w + rv*w6.w + cv*w7.w;
        bi.x += dv*w8.x + rv*w9.x + cv*wA.x;  bi.y += dv*w8.y + rv*w9.y + cv*wA.y;
        bi.z += dv*w8.z + rv*w9.z + cv*wA.z;  bi.w += dv*w8.w + rv*w9.w + cv*wA.w;
    }
    int f = fx * 4;
    const float4 dgc = *(const float4*)(g_dgc + b*Fq + f);
    const float4 bic = *(const float4*)(g_bic + b*Fq + f);
    dg.x += dgc.x; dg.y += dgc.y; dg.z += dgc.z; dg.w += dgc.w;
    bi.x += bic.x; bi.y += bic.y; bi.z += bic.z; bi.w += bic.w;
    *(float4*)(g_dg + row*Fq + f) = dg;
    *(float4*)(g_bj + row*Fq + f) = bj;
    *(float4*)(g_bi + row*Fq + f) = bi;
}

// ============================================================================
// tcgen05 path (sm_103a only): 1x TF32, double-buffered A + D, pipelined
// ============================================================================
#if HAS_TCGEN05
__device__ __forceinline__ uint32_t smem_u32(const void* p) {
    uint32_t a;
    asm("{ .reg .u64 t; cvta.to.shared.u64 t, %1; cvt.u32.u64 %0, t; }" : "=r"(a) : "l"(p));
    return a;
}
__device__ __forceinline__ uint32_t elect_one() {
    uint32_t p;
    asm volatile("{\n\t.reg .pred p;\n\telect.sync _|p, 0xFFFFFFFF;\n\tselp.b32 %0, 1, 0, p;\n\t}" : "=r"(p));
    return p;
}
__device__ __forceinline__ float tf32_rna(float x) {
    uint32_t r;
    asm("cvt.rna.tf32.f32 %0, %1;" : "=r"(r) : "f"(x));
    return __uint_as_float(r);
}
__device__ __forceinline__ void mma_tf32_ss(uint32_t d, uint64_t ad, uint64_t bd,
                                            uint32_t idesc, uint32_t en) {
    asm volatile(
        "{\n\t.reg .pred p;\n\tsetp.ne.u32 p, %4, 0;\n\t"
        "tcgen05.mma.cta_group::1.kind::tf32 [%0], %1, %2, %3, {%5, %5, %5, %5}, p;\n\t}"
        :: "r"(d), "l"(ad), "l"(bd), "r"(idesc), "r"(en), "r"(0u) : "memory");
}
#define TC_ALLOC(sm, n)   asm volatile("tcgen05.alloc.cta_group::1.sync.aligned.shared::cta.b32 [%0], %1;" :: "r"(sm), "r"(n) : "memory")
#define TC_DEALLOC(t, n)  asm volatile("tcgen05.dealloc.cta_group::1.sync.aligned.b32 %0, %1;" :: "r"(t), "r"(n))
#define TC_RELINQ()       asm volatile("tcgen05.relinquish_alloc_permit.cta_group::1.sync.aligned;")
#define TC_COMMIT(mb)     asm volatile("tcgen05.commit.cta_group::1.mbarrier::arrive::one.shared::cluster.b64 [%0];" :: "r"(mb) : "memory")
#define TC_WAIT_LD()      asm volatile("tcgen05.wait::ld.sync.aligned;" ::: "memory")
#define TC_FENCE_BEFORE() asm volatile("tcgen05.fence::before_thread_sync;" ::: "memory")
#define TC_FENCE_AFTER()  asm volatile("tcgen05.fence::after_thread_sync;" ::: "memory")
#define FENCE_ASYNC()     asm volatile("fence.proxy.async.shared::cta;" ::: "memory")
#define MBAR_INIT(mb, c)  asm volatile("mbarrier.init.shared.b64 [%0], %1;" :: "r"(mb), "r"(c) : "memory")
#define MBAR_INVAL(mb)    asm volatile("mbarrier.inval.shared.b64 [%0];" :: "r"(mb) : "memory")
__device__ __forceinline__ void mbar_wait(uint32_t mb, uint32_t ph) {
    uint32_t done;
    asm volatile(
        "{\n\t.reg .pred p;\n\t"
        "mbarrier.try_wait.parity.acquire.cta.shared::cta.b64 p, [%1], %2;\n\t"
        "selp.b32 %0, 1, 0, p;\n\t}"
        : "=r"(done) : "r"(mb), "r"(ph) : "memory");
    if (!done) {
        asm volatile(
            "{\n\t.reg .pred P1;\n\t"
            "WL_%=:\n\t"
            "mbarrier.try_wait.parity.acquire.cta.shared::cta.b64 P1, [%0], %1, 0x989680;\n\t"
            "@P1 bra.uni WD_%=;\n\t"
            "bra.uni WL_%=;\n\t"
            "WD_%=:\n\t}"
            :: "r"(mb), "r"(ph) : "memory");
    }
}
#define LDTM_X32(r, a) \
    asm volatile("tcgen05.ld.sync.aligned.32x32b.x32.b32 " \
        "{%0, %1, %2, %3, %4, %5, %6, %7, %8, %9, %10, %11, %12, %13, %14, %15, " \
        " %16, %17, %18, %19, %20, %21, %22, %23, %24, %25, %26, %27, %28, %29, %30, %31}, [%32];" \
        : "=r"((r)[0]),  "=r"((r)[1]),  "=r"((r)[2]),  "=r"((r)[3]), \
          "=r"((r)[4]),  "=r"((r)[5]),  "=r"((r)[6]),  "=r"((r)[7]), \
          "=r"((r)[8]),  "=r"((r)[9]),  "=r"((r)[10]), "=r"((r)[11]), \
          "=r"((r)[12]), "=r"((r)[13]), "=r"((r)[14]), "=r"((r)[15]), \
          "=r"((r)[16]), "=r"((r)[17]), "=r"((r)[18]), "=r"((r)[19]), \
          "=r"((r)[20]), "=r"((r)[21]), "=r"((r)[22]), "=r"((r)[23]), \
          "=r"((r)[24]), "=r"((r)[25]), "=r"((r)[26]), "=r"((r)[27]), \
          "=r"((r)[28]), "=r"((r)[29]), "=r"((r)[30]), "=r"((r)[31]) \
        : "r"(a))

static constexpr uint64_t DESC_BASE_SW128 =
    (uint64_t(2) << 61) | (uint64_t(1) << 46) | (uint64_t(64) << 32) | (uint64_t(1) << 16);
#define MK_DESC(addr) (DESC_BASE_SW128 | ((uint64_t)((addr) >> 4) & 0x3FFF))
#define IDESC_TF32 ((1u<<4) | (2u<<7) | (2u<<10) | (12u<<17) | (8u<<24))

__device__ __forceinline__ uint32_t a_off(int row, int k) {
    uint32_t o = ((k >> 5) * 16384u) + (uint32_t)row * 128u + ((k & 31) << 2);
    return o ^ ((o >> 3) & 0x70u);
}
__device__ __forceinline__ uint32_t b_off(int n, int k) {
    uint32_t o = ((k >> 5) * 12288u) + (uint32_t)n * 128u + ((k & 31) << 2);
    return o ^ ((o >> 3) & 0x70u);
}
__device__ __forceinline__ uint64_t acd(int c) { return (uint64_t)((c >> 2) * 1024 + (c & 3) * 2); }
__device__ __forceinline__ uint64_t bcd(int c) { return (uint64_t)((c >> 2) * 768  + (c & 3) * 2); }
#endif // HAS_TCGEN05

// SMEM layout
#define OFF_TMEM 0
#define OFF_MBAR 16
#define OFF_B12  1024
#define OFF_B11  (OFF_B12 + 24576)
#define OFF_AS0  (OFF_B11 + 24576)
#define OFF_AT0  (OFF_AS0 + 32768)
#define OFF_AS1  (OFF_AT0 + 32768)
#define OFF_AT1  (OFF_AS1 + 32768)
#define SMEM_TOT (OFF_AT1 + 32768 + 64)

#if HAS_TCGEN05
// stage one (As, At) pair; caller picks thread set: t in [0, nthr)
__device__ __forceinline__ void stage_pair(char* sm, uint32_t as_off, uint32_t at_off,
                                           const float* __restrict__ x,
                                           int b, int i, int j0, int t, int nthr) {
    const float4* xs4 = (const float4*)(x + (((long)b*Nq + i)*Nq + j0)*Lq);
    const float* xt0  = x + ((long)b*Nq + j0)*Nq*Lq + (long)i*Lq;
    int steps = 1536 / nthr;
    #pragma unroll
    for (int q = 0; q < 12; q++) {
        if (q >= steps) break;
        int idx4 = t + nthr*q;
        int r = idx4 / 12, l4 = idx4 % 12;
        float4 v = xs4[idx4];
        float4 h;
        h.x = tf32_rna(v.x); h.y = tf32_rna(v.y); h.z = tf32_rna(v.z); h.w = tf32_rna(v.w);
        *(float4*)(sm + as_off + a_off(r, l4*4)) = h;
        float4 u = *(const float4*)(xt0 + (long)r*Nq*Lq + l4*4);
        float4 g;
        g.x = tf32_rna(u.x); g.y = tf32_rna(u.y); g.z = tf32_rna(u.z); g.w = tf32_rna(u.w);
        *(float4*)(sm + at_off + a_off(r, l4*4)) = g;
    }
}

__device__ __forceinline__ void issue_group(uint32_t tmem_d, uint64_t dAs, uint64_t dAt,
                                            uint64_t dB12, uint64_t dB11, uint32_t mb) {
    uint32_t en = 0;
    #pragma unroll
    for (int c = 0; c < 6; c++) { mma_tf32_ss(tmem_d, dAs + acd(c), dB12 + bcd(c), IDESC_TF32, en); en = 1; }
    #pragma unroll
    for (int c = 0; c < 6; c++)   mma_tf32_ss(tmem_d, dAt + acd(c), dB11 + bcd(c), IDESC_TF32, 1);
    TC_COMMIT(mb);
}
#endif

// grid 128: b = blk>>4, jt = (blk>>3)&1, ic = blk&7; 32 i-iters per block.
__global__ void __launch_bounds__(256, 1) k_mma(const float* __restrict__ x,
                                                const float* __restrict__ w,
                                                float* __restrict__ out) {
#if HAS_TCGEN05
    extern __shared__ char sm[];
    uint32_t smb = smem_u32(sm);
    int tid = threadIdx.x;
    int wid = tid >> 5;

    int blk = blockIdx.x;
    int b = blk >> 4, jt = (blk >> 3) & 1, ic = blk & 7;
    int j0 = jt * 128;

    if (wid == 0) TC_ALLOC(smb + OFF_TMEM, 256);
    __syncthreads();
    uint32_t tmem;
    asm volatile("ld.shared.b32 %0, [%1];" : "=r"(tmem) : "r"(smb + OFF_TMEM));

    if (tid == 0) { MBAR_INIT(smb + OFF_MBAR, 1); MBAR_INIT(smb + OFF_MBAR + 8, 1); }

    // B tiles (K-major SW128 blocked atoms), tf32-rounded
    for (int idx = tid; idx < Lq*Fq; idx += 256) {
        int f = idx / Lq, l = idx % Lq;
        *(float*)(sm + OFF_B12 + b_off(f, l)) = tf32_rna(w[12*LF + l*Fq + f]);
        *(float*)(sm + OFF_B11 + b_off(f, l)) = tf32_rna(w[11*LF + l*Fq + f]);
    }

    uint64_t dA[2][2] = {{MK_DESC(smb + OFF_AS0), MK_DESC(smb + OFF_AT0)},
                         {MK_DESC(smb + OFF_AS1), MK_DESC(smb + OFF_AT1)}};
    uint32_t aoff_s[2] = {OFF_AS0, OFF_AS1};
    uint32_t aoff_t[2] = {OFF_AT0, OFF_AT1};
    uint64_t dB12 = MK_DESC(smb + OFF_B12);
    uint64_t dB11 = MK_DESC(smb + OFF_B11);

    // prologue: stage A(0) (all threads), issue MMA(0), stage A(1)
    stage_pair(sm, OFF_AS0, OFF_AT0, x, b, ic*32 + 0, j0, tid, 256);
    FENCE_ASYNC();
    __syncthreads();
    if (wid == 4 && elect_one()) {
        TC_FENCE_AFTER();
        issue_group(tmem, dA[0][0], dA[0][1], dB12, dB11, smb + OFF_MBAR);
    }
    stage_pair(sm, OFF_AS1, OFF_AT1, x, b, ic*32 + 1, j0, tid, 256);
    FENCE_ASYNC();
    __syncthreads();

    uint32_t ph[2] = {0, 0};

    for (int it = 0; it < 32; it++) {
        int i = ic*32 + it;
        int cur = it & 1;

        // issue next MMA (overlaps with wait/epilogue/staging below)
        if (it < 31 && wid == 4 && elect_one()) {
            int nxt = cur ^ 1;
            issue_group(tmem + nxt*128, dA[nxt][0], dA[nxt][1], dB12, dB11,
                        smb + OFF_MBAR + nxt*8);
        }

        mbar_wait(smb + OFF_MBAR + cur*8, ph[cur]);
        ph[cur] ^= 1;
        TC_FENCE_AFTER();

        if (tid < 128) {
            // epilogue: read D(cur), add biases, store
            uint32_t d[96];
            uint32_t td = tmem + cur*128;
            LDTM_X32(d,      td);
            LDTM_X32(d + 32, td + 32);
            LDTM_X32(d + 64, td + 64);
            TC_WAIT_LD();
            int j = j0 + tid;
            const float4* bj4 = (const float4*)(g_bj + ((long)b*Nq + j)*Fq);
            const float4* bi4 = (const float4*)(g_bi + ((long)b*Nq + i)*Fq);
            const float4* dg4 = (const float4*)(g_dg + ((long)b*Nq + i)*Fq);
            float4* op = (float4*)(out + (((long)b*Nq + i)*Nq + j)*Fq);
            bool isd = (j == i);
            #pragma unroll
            for (int q = 0; q < 24; q++) {
                float4 bv = bj4[q], iv = bi4[q];
                float4 o;
                o.x = __uint_as_float(d[4*q+0]) + iv.x + bv.x;
                o.y = __uint_as_float(d[4*q+1]) + iv.y + bv.y;
                o.z = __uint_as_float(d[4*q+2]) + iv.z + bv.z;
                o.w = __uint_as_float(d[4*q+3]) + iv.w + bv.w;
                if (isd) {
                    float4 gv = dg4[q];
                    o.x += gv.x; o.y += gv.y; o.z += gv.z; o.w += gv.w;
                }
                op[q] = o;
            }
            TC_FENCE_BEFORE();
        } else if (it + 2 < 32) {
            // stage A(it+2) into buffer 'cur' (MMA(it) done reading it)
            stage_pair(sm, aoff_s[cur], aoff_t[cur], x, b, ic*32 + it + 2, j0, tid - 128, 128);
            FENCE_ASYNC();
        }
        __syncthreads();
    }

    if (tid == 0) { MBAR_INVAL(smb + OFF_MBAR); MBAR_INVAL(smb + OFF_MBAR + 8); }
    __syncthreads();
    if (wid == 0) {
        TC_RELINQ();
        TC_DEALLOC(tmem, 256);
    }
#endif // HAS_TCGEN05
}

// ============================================================================
// CUDA-core fallback dense kernel (active only when tcgen05 is unavailable)
// ============================================================================
__global__ void __launch_bounds__(512) k_main_fb(const float* __restrict__ x,
                                                 const float* __restrict__ w,
                                                 float* __restrict__ out) {
#if !HAS_TCGEN05
    __shared__ __align__(16) float s_w12[LF];
    __shared__ __align__(16) float s_w11[LF];
    __shared__ __align__(16) float s_bi[Fq];
    __shared__ __align__(16) float s_dg[Fq];

    int blk = blockIdx.x; int b = blk >> 8, i = blk & 255;
    int tid = threadIdx.x;
    int j = tid >> 1, fh = tid & 1;

    for (int t = tid; t < LF; t += 512) {
        s_w11[t] = w[11*LF + t];
        s_w12[t] = w[12*LF + t];
    }
    {
        int rb = (b*Nq + i)*Fq;
        if (tid < Fq)            s_bi[tid]        = g_bi[rb + tid];
        else if (tid < 2*Fq)     s_dg[tid - Fq]   = g_dg[rb + tid - Fq];
    }
    __syncthreads();

    const float4* xa4 = (const float4*)(x + (((long)b*Nq + i)*Nq + j)*Lq);
    const float4* xb4 = (const float4*)(x + (((long)b*Nq + j)*Nq + i)*Lq);
    const ulonglong2* w12v = ((const ulonglong2*)s_w12) + fh*12;
    const ulonglong2* w11v = ((const ulonglong2*)s_w11) + fh*12;

    unsigned long long acc[24];
    #pragma unroll
    for (int q = 0; q < 24; q++) acc[q] = 0ull;

    for (int l4 = 0; l4 < 12; l4++) {
        float4 av = xa4[l4];
        float4 bv = xb4[l4];
        #pragma unroll
        for (int k = 0; k < 4; k++) {
            int l = l4*4 + k;
            float afl = (k==0) ? av.x : (k==1) ? av.y : (k==2) ? av.z : av.w;
            float bfl = (k==0) ? bv.x : (k==1) ? bv.y : (k==2) ? bv.z : bv.w;
            unsigned long long xa2 = pack2(afl);
            unsigned long long xb2 = pack2(bfl);
            const ulonglong2* wa = w12v + l*24;
            const ulonglong2* wb = w11v + l*24;
            #pragma unroll
            for (int q = 0; q < 12; q++) {
                ulonglong2 va = wa[q];
                acc[2*q]   = ffma2(xa2, va.x, acc[2*q]);
                acc[2*q+1] = ffma2(xa2, va.y, acc[2*q+1]);
            }
            #pragma unroll
            for (int q = 0; q < 12; q++) {
                ulonglong2 vb = wb[q];
                acc[2*q]   = ffma2(xb2, vb.x, acc[2*q]);
                acc[2*q+1] = ffma2(xb2, vb.y, acc[2*q+1]);
            }
        }
    }

    int f0 = fh * 48;
    const float4* bj4 = (const float4*)(g_bj + (b*Nq + j)*Fq + f0);
    float* orow = out + ((((long)b*Nq + i)*Nq + j)*Fq) + f0;
    bool isd = (i == j);
    #pragma unroll
    for (int q = 0; q < 12; q++) {
        float2 a  = *(float2*)(&acc[2*q]);
        float2 bb = *(float2*)(&acc[2*q+1]);
        float4 bjv = bj4[q];
        int f = 4*q;
        float4 o;
        o.x = a.x  + s_bi[f0+f]   + bjv.x;
        o.y = a.y  + s_bi[f0+f+1] + bjv.y;
        o.z = bb.x + s_bi[f0+f+2] + bjv.z;
        o.w = bb.y + s_bi[f0+f+3] + bjv.w;
        if (isd) {
            o.x += s_dg[f0+f];   o.y += s_dg[f0+f+1];
            o.z += s_dg[f0+f+2]; o.w += s_dg[f0+f+3];
        }
        *(float4*)(orow + f) = o;
    }
#endif // !HAS_TCGEN05
}

// ---------------- launch ----------------
extern "C" void kernel_launch(void* const* d_in, const int* in_sizes, int n_in,
                              void* d_out, int out_size) {
    const float* x = (const float*)d_in[0];
    const float* w = (const float*)d_in[1];
    if (n_in >= 2 && in_sizes[0] == 15*Lq*Fq) {
        x = (const float*)d_in[1];
        w = (const float*)d_in[0];
    }
    float* out = (float*)d_out;

    cudaFuncSetAttribute(k_mma, cudaFuncAttributeMaxDynamicSharedMemorySize, SMEM_TOT);

    k_rowsum<<<Bq*Nq, 384>>>(x);
    k_colsum<<<Bq*32, 384>>>(x);
    k_trace<<<Bq, 2*Lq>>>(w);
    k_small<<<128, 384>>>(w);
    k_mma<<<128, 256, SMEM_TOT>>>(x, w, out);       // work iff tcgen05 available
    k_main_fb<<<Bq*Nq, 512>>>(x, w, out);           // work iff NOT available
}

// round 11
// speedup vs baseline: 1.6591x; 1.1543x over previous
#include <cuda_runtime.h>
#include <cuda.h>
#include <cstdint>

#define Bq 8
#define Nq 256
#define Lq 48
#define Fq 96
#define LF (Lq*Fq)

#if defined(__CUDA_ARCH__) && (__CUDA_ARCH__ == 1030) && \
    (defined(__CUDA_ARCH_FEAT_SM103_ALL) || defined(__CUDA_ARCH_SPECIFIC__) || defined(__CUDA_ARCH_FAMILY_SPECIFIC__))
#define HAS_TCGEN05 1
#else
#define HAS_TCGEN05 0
#endif

// ---------------- scratch ----------------
__device__ __align__(16) float g_rowsum[Bq*Nq*Lq];
__device__ __align__(16) float g_colsum[Bq*Nq*Lq];
__device__ __align__(16) float g_diag[Bq*Nq*Lq];
__device__ __align__(16) float g_dgc[Bq*Fq];
__device__ __align__(16) float g_bic[Bq*Fq];
__device__ __align__(16) float g_bi[Bq*Nq*Fq];
__device__ __align__(16) float g_bj[Bq*Nq*Fq];
__device__ __align__(16) float g_dg[Bq*Nq*Fq];

// ---------------- generic helpers ----------------
__device__ __forceinline__ unsigned long long ffma2(unsigned long long a,
                                                    unsigned long long b,
                                                    unsigned long long c) {
    unsigned long long d;
    asm("fma.rn.f32x2 %0, %1, %2, %3;" : "=l"(d) : "l"(a), "l"(b), "l"(c));
    return d;
}
__device__ __forceinline__ unsigned long long pack2(float v) {
    unsigned long long r;
    asm("mov.b64 %0, {%1, %1};" : "=l"(r) : "f"(v));
    return r;
}

// ---------------- pass 1a: rowsum + diag ----------------
__global__ void k_rowsum(const float* __restrict__ x) {
    int blk = blockIdx.x; int b = blk >> 8, i = blk & 255;
    int tid = threadIdx.x;               // 384
    int l = tid % Lq, ys = tid / Lq;
    const float* base = x + (((long)b*Nq + i) * Nq) * Lq;
    float acc = 0.f;
    #pragma unroll 4
    for (int s = 0; s < 32; s++) acc += base[(ys*32 + s)*Lq + l];
    __shared__ float sp[8][Lq];
    sp[ys][l] = acc;
    __syncthreads();
    if (tid < Lq) {
        float r = 0.f;
        #pragma unroll
        for (int y = 0; y < 8; y++) r += sp[y][tid];
        g_rowsum[(b*Nq + i)*Lq + tid] = r;
        g_diag[(b*Nq + i)*Lq + tid]   = base[i*Lq + tid];
    }
}

// ---------------- pass 1b: colsum ----------------
__global__ void k_colsum(const float* __restrict__ x) {
    int blk = blockIdx.x; int b = blk >> 5, jt = blk & 31;
    int tid = threadIdx.x;               // 384
    int l = tid % Lq, y = tid / Lq;
    int j = jt * 8 + y;
    const float* base = x + ((long)b*Nq*Nq + (long)j) * Lq + l;
    float acc = 0.f;
    #pragma unroll 8
    for (int i = 0; i < Nq; i++) acc += base[(long)i * Nq * Lq];
    g_colsum[(b*Nq + j)*Lq + l] = acc;
}

// ---------------- pass 1c: trace/totsum -> per-b F constants ----------------
__global__ void k_trace(const float* __restrict__ w) {
    int b = blockIdx.x; int t = threadIdx.x;   // 96 threads
    __shared__ float s_tr[Lq], s_ts[Lq];
    if (t < Lq) {
        float a = 0.f;
        #pragma unroll 8
        for (int i = 0; i < Nq; i++) a += g_diag[(b*Nq + i)*Lq + t];
        s_tr[t] = a;
    } else {
        int l = t - Lq;
        float a = 0.f;
        #pragma unroll 8
        for (int i = 0; i < Nq; i++) a += g_rowsum[(b*Nq + i)*Lq + l];
        s_ts[l] = a;
    }
    __syncthreads();
    float dgc = 0.f, bic = 0.f;
    #pragma unroll 4
    for (int l = 0; l < Lq; l++) {
        float tr = s_tr[l], ts = s_ts[l];
        dgc += tr * w[3*LF  + l*Fq + t] + ts * w[4*LF  + l*Fq + t];
        bic += tr * w[13*LF + l*Fq + t] + ts * w[14*LF + l*Fq + t];
    }
    g_dgc[b*Fq + t] = dgc;
    g_bic[b*Fq + t] = bic;
}

// ---------------- pass 2: small GEMMs -> bi/bj/dg ----------------
__global__ void __launch_bounds__(192) k_small(const float* __restrict__ w) {
    __shared__ float sd[8][Lq], sr[8][Lq], sc[8][Lq];
    int row0 = blockIdx.x * 8;
    int tid = threadIdx.x;               // 192 = 24 fx * 8 y
    for (int idx = tid; idx < 8*Lq; idx += 192) {
        int r = idx / Lq, l = idx % Lq;
        sd[r][l] = g_diag  [(row0 + r)*Lq + l];
        sr[r][l] = g_rowsum[(row0 + r)*Lq + l];
        sc[r][l] = g_colsum[(row0 + r)*Lq + l];
    }
    __syncthreads();
    int fx = tid % 24, y = tid / 24;
    int row = row0 + y; int b = row >> 8;
    float4 dg = {0,0,0,0}, bj = {0,0,0,0}, bi = {0,0,0,0};
    const float4* w4 = (const float4*)w;
    #pragma unroll 4
    for (int l = 0; l < Lq; l++) {
        float dv = sd[y][l], rv = sr[y][l], cv = sc[y][l];
        int base = (l*Fq)/4 + fx;
        float4 w0 = w4[base + (0*LF)/4],  w1 = w4[base + (1*LF)/4],  w2 = w4[base + (2*LF)/4];
        float4 w5 = w4[base + (5*LF)/4],  w6 = w4[base + (6*LF)/4],  w7 = w4[base + (7*LF)/4];
        float4 w8 = w4[base + (8*LF)/4],  w9 = w4[base + (9*LF)/4],  wA = w4[base + (10*LF)/4];
        dg.x += dv*w0.x + rv*w1.x + cv*w2.x;  dg.y += dv*w0.y + rv*w1.y + cv*w2.y;
        dg.z += dv*w0.z + rv*w1.z + cv*w2.z;  dg.w += dv*w0.w + rv*w1.w + cv*w2.w;
        bj.x += dv*w5.x + rv*w6.x + cv*w7.x;  bj.y += dv*w5.y + rv*w6.y + cv*w7.y;
        bj.z += dv*w5.z + rv*w6.z + cv*w7.z;  bj.w += dv*w5.w + rv*w6.w + cv*w7.w;
        bi.x += dv*w8.x + rv*w9.x + cv*wA.x;  bi.y += dv*w8.y + rv*w9.y + cv*wA.y;
        bi.z += dv*w8.z + rv*w9.z + cv*wA.z;  bi.w += dv*w8.w + rv*w9.w + cv*wA.w;
    }
    int f = fx * 4;
    const float4 dgc = *(const float4*)(g_dgc + b*Fq + f);
    const float4 bic = *(const float4*)(g_bic + b*Fq + f);
    dg.x += dgc.x; dg.y += dgc.y; dg.z += dgc.z; dg.w += dgc.w;
    bi.x += bic.x; bi.y += bic.y; bi.z += bic.z; bi.w += bic.w;
    *(float4*)(g_dg + row*Fq + f) = dg;
    *(float4*)(g_bj + row*Fq + f) = bj;
    *(float4*)(g_bi + row*Fq + f) = bi;
}

// ============================================================================
// tcgen05 path: TMA(SW128) staging of raw fp32, tf32 MMA, pipelined
// ============================================================================
#if HAS_TCGEN05
__device__ __forceinline__ uint32_t smem_u32(const void* p) {
    uint32_t a;
    asm("{ .reg .u64 t; cvta.to.shared.u64 t, %1; cvt.u32.u64 %0, t; }" : "=r"(a) : "l"(p));
    return a;
}
__device__ __forceinline__ float tf32_rna(float x) {
    uint32_t r;
    asm("cvt.rna.tf32.f32 %0, %1;" : "=r"(r) : "f"(x));
    return __uint_as_float(r);
}
__device__ __forceinline__ void mma_tf32_ss(uint32_t d, uint64_t ad, uint64_t bd,
                                            uint32_t idesc, uint32_t en) {
    asm volatile(
        "{\n\t.reg .pred p;\n\tsetp.ne.u32 p, %4, 0;\n\t"
        "tcgen05.mma.cta_group::1.kind::tf32 [%0], %1, %2, %3, {%5, %5, %5, %5}, p;\n\t}"
        :: "r"(d), "l"(ad), "l"(bd), "r"(idesc), "r"(en), "r"(0u) : "memory");
}
#define TMA4(dst, map, c0, c1, c2, c3, mb) \
    asm volatile("cp.async.bulk.tensor.4d.shared::cta.global.tile.mbarrier::complete_tx::bytes " \
        "[%0], [%1, {%2, %3, %4, %5}], [%6];" \
        :: "r"(dst), "l"(map), "r"(c0), "r"(c1), "r"(c2), "r"(c3), "r"(mb) : "memory")
#define TC_ALLOC(sm, n)   asm volatile("tcgen05.alloc.cta_group::1.sync.aligned.shared::cta.b32 [%0], %1;" :: "r"(sm), "r"(n) : "memory")
#define TC_DEALLOC(t, n)  asm volatile("tcgen05.dealloc.cta_group::1.sync.aligned.b32 %0, %1;" :: "r"(t), "r"(n))
#define TC_RELINQ()       asm volatile("tcgen05.relinquish_alloc_permit.cta_group::1.sync.aligned;")
#define TC_COMMIT(mb)     asm volatile("tcgen05.commit.cta_group::1.mbarrier::arrive::one.shared::cluster.b64 [%0];" :: "r"(mb) : "memory")
#define TC_WAIT_LD()      asm volatile("tcgen05.wait::ld.sync.aligned;" ::: "memory")
#define TC_FENCE_BEFORE() asm volatile("tcgen05.fence::before_thread_sync;" ::: "memory")
#define TC_FENCE_AFTER()  asm volatile("tcgen05.fence::after_thread_sync;" ::: "memory")
#define FENCE_ASYNC()     asm volatile("fence.proxy.async.shared::cta;" ::: "memory")
#define MBAR_INIT(mb, c)  asm volatile("mbarrier.init.shared.b64 [%0], %1;" :: "r"(mb), "r"(c) : "memory")
#define MBAR_INVAL(mb)    asm volatile("mbarrier.inval.shared.b64 [%0];" :: "r"(mb) : "memory")
#define MBAR_EXPECT(mb, n) asm volatile("mbarrier.arrive.expect_tx.shared.b64 _, [%0], %1;" :: "r"(mb), "r"(n) : "memory")
__device__ __forceinline__ void mbar_wait(uint32_t mb, uint32_t ph) {
    uint32_t done;
    asm volatile(
        "{\n\t.reg .pred p;\n\t"
        "mbarrier.try_wait.parity.acquire.cta.shared::cta.b64 p, [%1], %2;\n\t"
        "selp.b32 %0, 1, 0, p;\n\t}"
        : "=r"(done) : "r"(mb), "r"(ph) : "memory");
    if (!done) {
        asm volatile(
            "{\n\t.reg .pred P1;\n\t"
            "WL_%=:\n\t"
            "mbarrier.try_wait.parity.acquire.cta.shared::cta.b64 P1, [%0], %1, 0x989680;\n\t"
            "@P1 bra.uni WD_%=;\n\t"
            "bra.uni WL_%=;\n\t"
            "WD_%=:\n\t}"
            :: "r"(mb), "r"(ph) : "memory");
    }
}
#define LDTM_X32(r, a) \
    asm volatile("tcgen05.ld.sync.aligned.32x32b.x32.b32 " \
        "{%0, %1, %2, %3, %4, %5, %6, %7, %8, %9, %10, %11, %12, %13, %14, %15, " \
        " %16, %17, %18, %19, %20, %21, %22, %23, %24, %25, %26, %27, %28, %29, %30, %31}, [%32];" \
        : "=r"((r)[0]),  "=r"((r)[1]),  "=r"((r)[2]),  "=r"((r)[3]), \
          "=r"((r)[4]),  "=r"((r)[5]),  "=r"((r)[6]),  "=r"((r)[7]), \
          "=r"((r)[8]),  "=r"((r)[9]),  "=r"((r)[10]), "=r"((r)[11]), \
          "=r"((r)[12]), "=r"((r)[13]), "=r"((r)[14]), "=r"((r)[15]), \
          "=r"((r)[16]), "=r"((r)[17]), "=r"((r)[18]), "=r"((r)[19]), \
          "=r"((r)[20]), "=r"((r)[21]), "=r"((r)[22]), "=r"((r)[23]), \
          "=r"((r)[24]), "=r"((r)[25]), "=r"((r)[26]), "=r"((r)[27]), \
          "=r"((r)[28]), "=r"((r)[29]), "=r"((r)[30]), "=r"((r)[31]) \
        : "r"(a))
#define LDTM_X16(r, a) \
    asm volatile("tcgen05.ld.sync.aligned.32x32b.x16.b32 " \
        "{%0, %1, %2, %3, %4, %5, %6, %7, %8, %9, %10, %11, %12, %13, %14, %15}, [%16];" \
        : "=r"((r)[0]),  "=r"((r)[1]),  "=r"((r)[2]),  "=r"((r)[3]), \
          "=r"((r)[4]),  "=r"((r)[5]),  "=r"((r)[6]),  "=r"((r)[7]), \
          "=r"((r)[8]),  "=r"((r)[9]),  "=r"((r)[10]), "=r"((r)[11]), \
          "=r"((r)[12]), "=r"((r)[13]), "=r"((r)[14]), "=r"((r)[15]) \
        : "r"(a))

// K-major SW128 descriptors (validated R2-R4): LBO=1, SBO=64
static constexpr uint64_t DESC_SW128 =
    (uint64_t(2) << 61) | (uint64_t(1) << 46) | (uint64_t(64) << 32) | (uint64_t(1) << 16);
#define MK_DESC(addr) (DESC_SW128 | ((uint64_t)((addr) >> 4) & 0x3FFF))
#define IDESC_TF32 ((1u<<4) | (2u<<7) | (2u<<10) | (12u<<17) | (8u<<24))

__device__ __forceinline__ uint32_t b_off(int n, int k) {
    uint32_t o = ((k >> 5) * 12288u) + (uint32_t)n * 128u + ((k & 31) << 2);
    return o ^ ((o >> 3) & 0x70u);
}
#endif // HAS_TCGEN05

// SMEM layout
#define A_TILE_SZ 32768               // two 16KB SW128 k-blocks
#define OFF_TMEM  0
#define OFF_MBAR  16                  // 4 mbars: tma0, tma1, mma0, mma1
#define OFF_B12   1024
#define OFF_B11   (OFF_B12 + 24576)
#define OFF_A     (OFF_B11 + 24576)   // 4 tiles: As0, At0, As1, At1
#define SMEM_TOT  (OFF_A + 4*A_TILE_SZ + 128)

#if HAS_TCGEN05
__device__ __forceinline__ void issue_group(uint32_t tmem_d, uint64_t dAs, uint64_t dAt,
                                            uint64_t dB12, uint64_t dB11, uint32_t mb) {
    // A chunk offsets (16B units): block0 k{0,8,16,24}; block1 holds k32..63 -> k32@+1028, k40@+1030
    const uint64_t acd[6] = {0, 2, 4, 6, 1024 + 4, 1024 + 6};
    const uint64_t bcd[6] = {0, 2, 4, 6, 768 + 0, 768 + 2};
    uint32_t en = 0;
    #pragma unroll
    for (int c = 0; c < 6; c++) { mma_tf32_ss(tmem_d, dAs + acd[c], dB12 + bcd[c], IDESC_TF32, en); en = 1; }
    #pragma unroll
    for (int c = 0; c < 6; c++)   mma_tf32_ss(tmem_d, dAt + acd[c], dB11 + bcd[c], IDESC_TF32, 1);
    TC_COMMIT(mb);
}

// single-thread: TMA-stage iteration ii into stage buffer s
__device__ __forceinline__ void issue_stage(uint32_t smb, const CUtensorMap* mapS,
                                            const CUtensorMap* mapT,
                                            int b, int ii, int j0, int s) {
    uint32_t mb = smb + OFF_MBAR + s*8;
    MBAR_EXPECT(mb, 4*16384);
    uint32_t as = smb + OFF_A + (2*s + 0)*A_TILE_SZ;
    uint32_t at = smb + OFF_A + (2*s + 1)*A_TILE_SZ;
    TMA4(as,         mapS, 0,  j0, ii, b, mb);
    TMA4(as + 16384, mapS, 16, j0, ii, b, mb);
    TMA4(at,         mapT, 0,  j0, ii, b, mb);
    TMA4(at + 16384, mapT, 16, j0, ii, b, mb);
}
#endif

// grid 128: b = blk>>4, jt = (blk>>3)&1, ic = blk&7; 32 i-iters per block.
__global__ void __launch_bounds__(256, 1) k_mma(const __grid_constant__ CUtensorMap mapS,
                                                const __grid_constant__ CUtensorMap mapT,
                                                const float* __restrict__ x,
                                                const float* __restrict__ w,
                                                float* __restrict__ out) {
#if HAS_TCGEN05
    extern __shared__ char sm[];
    uint32_t smb = smem_u32(sm);
    int tid = threadIdx.x;
    int wid = tid >> 5, lane = tid & 31;

    int blk = blockIdx.x;
    int b = blk >> 4, jt = (blk >> 3) & 1, ic = blk & 7;
    int j0 = jt * 128;

    if (wid == 0) TC_ALLOC(smb + OFF_TMEM, 256);
    __syncthreads();
    uint32_t tmem;
    asm volatile("ld.shared.b32 %0, [%1];" : "=r"(tmem) : "r"(smb + OFF_TMEM));

    if (tid == 0) {
        MBAR_INIT(smb + OFF_MBAR + 0,  1);   // tma_full[0]
        MBAR_INIT(smb + OFF_MBAR + 8,  1);   // tma_full[1]
        MBAR_INIT(smb + OFF_MBAR + 16, 1);   // mma_done[0]
        MBAR_INIT(smb + OFF_MBAR + 24, 1);   // mma_done[1]
    }

    // B tiles (K-major SW128), tf32-rounded via registers
    for (int idx = tid; idx < Lq*Fq; idx += 256) {
        int f = idx / Lq, l = idx % Lq;
        *(float*)(sm + OFF_B12 + b_off(f, l)) = tf32_rna(w[12*LF + l*Fq + f]);
        *(float*)(sm + OFF_B11 + b_off(f, l)) = tf32_rna(w[11*LF + l*Fq + f]);
    }
    FENCE_ASYNC();
    __syncthreads();

    uint64_t dAs[2] = {MK_DESC(smb + OFF_A + 0*A_TILE_SZ), MK_DESC(smb + OFF_A + 2*A_TILE_SZ)};
    uint64_t dAt[2] = {MK_DESC(smb + OFF_A + 1*A_TILE_SZ), MK_DESC(smb + OFF_A + 3*A_TILE_SZ)};
    uint64_t dB12 = MK_DESC(smb + OFF_B12);
    uint64_t dB11 = MK_DESC(smb + OFF_B11);

    uint32_t tph[2] = {0, 0}, mph[2] = {0, 0};

    // prologue: stage 0 and 1; MMA(0)
    if (tid == 0) {
        issue_stage(smb, &mapS, &mapT, b, ic*32 + 0, j0, 0);
        issue_stage(smb, &mapS, &mapT, b, ic*32 + 1, j0, 1);
        mbar_wait(smb + OFF_MBAR + 0, 0);
        issue_group(tmem, dAs[0], dAt[0], dB12, dB11, smb + OFF_MBAR + 16);
    }
    tph[0] = 1;

    int h = wid >> 2, sub = wid & 3;

    for (int it = 0; it < 32; it++) {
        int i = ic*32 + it;
        int cur = it & 1, nxt = cur ^ 1;

        // tid0: issue MMA(it+1) into D[nxt] once its stage is full
        if (tid == 0 && it + 1 < 32) {
            mbar_wait(smb + OFF_MBAR + nxt*8, tph[nxt]);
            issue_group(tmem + nxt*128, dAs[nxt], dAt[nxt], dB12, dB11,
                        smb + OFF_MBAR + 16 + nxt*8);
        }
        if (it + 1 < 32) tph[nxt] ^= 1;

        // all: wait MMA(it) done
        mbar_wait(smb + OFF_MBAR + 16 + cur*8, mph[cur]);
        mph[cur] ^= 1;
        TC_FENCE_AFTER();

        // tid0: refill smem buffer cur for iteration it+2 (A[cur] free now)
        if (tid == 0 && it + 2 < 32)
            issue_stage(smb, &mapS, &mapT, b, ic*32 + it + 2, j0, cur);

        // all 8 warps: read D[cur] (cols half h, rows = subpartition sub)
        uint32_t d[48];
        uint32_t td = tmem + cur*128 + h*48;
        LDTM_X32(d, td);
        LDTM_X16(d + 32, td + 32);
        TC_WAIT_LD();
        TC_FENCE_BEFORE();
        __syncthreads();           // D[cur] reads drained before MMA(it+2) issue

        int row = sub*32 + lane;
        int j = j0 + row;
        const float4* bj4 = (const float4*)(g_bj + ((long)b*Nq + j)*Fq + h*48);
        const float4* bi4 = (const float4*)(g_bi + ((long)b*Nq + i)*Fq + h*48);
        const float4* dg4 = (const float4*)(g_dg + ((long)b*Nq + i)*Fq + h*48);
        float4* op = (float4*)(out + (((long)b*Nq + i)*Nq + j)*Fq + h*48);
        bool isd = (j == i);
        #pragma unroll
        for (int q = 0; q < 12; q++) {
            float4 bv = bj4[q], iv = bi4[q];
            float4 o;
            o.x = __uint_as_float(d[4*q+0]) + iv.x + bv.x;
            o.y = __uint_as_float(d[4*q+1]) + iv.y + bv.y;
            o.z = __uint_as_float(d[4*q+2]) + iv.z + bv.z;
            o.w = __uint_as_float(d[4*q+3]) + iv.w + bv.w;
            if (isd) {
                float4 gv = dg4[q];
                o.x += gv.x; o.y += gv.y; o.z += gv.z; o.w += gv.w;
            }
            op[q] = o;
        }
    }

    __syncthreads();
    if (tid == 0) {
        MBAR_INVAL(smb + OFF_MBAR + 0);  MBAR_INVAL(smb + OFF_MBAR + 8);
        MBAR_INVAL(smb + OFF_MBAR + 16); MBAR_INVAL(smb + OFF_MBAR + 24);
    }
    __syncthreads();
    if (wid == 0) {
        TC_RELINQ();
        TC_DEALLOC(tmem, 256);
    }
#endif // HAS_TCGEN05
}

// ============================================================================
// CUDA-core fallback dense kernel (active only when tcgen05 is unavailable)
// ============================================================================
__global__ void __launch_bounds__(512) k_main_fb(const float* __restrict__ x,
                                                 const float* __restrict__ w,
                                                 float* __restrict__ out) {
#if !HAS_TCGEN05
    __shared__ __align__(16) float s_w12[LF];
    __shared__ __align__(16) float s_w11[LF];
    __shared__ __align__(16) float s_bi[Fq];
    __shared__ __align__(16) float s_dg[Fq];

    int blk = blockIdx.x; int b = blk >> 8, i = blk & 255;
    int tid = threadIdx.x;
    int j = tid >> 1, fh = tid & 1;

    for (int t = tid; t < LF; t += 512) {
        s_w11[t] = w[11*LF + t];
        s_w12[t] = w[12*LF + t];
    }
    {
        int rb = (b*Nq + i)*Fq;
        if (tid < Fq)            s_bi[tid]        = g_bi[rb + tid];
        else if (tid < 2*Fq)     s_dg[tid - Fq]   = g_dg[rb + tid - Fq];
    }
    __syncthreads();

    const float4* xa4 = (const float4*)(x + (((long)b*Nq + i)*Nq + j)*Lq);
    const float4* xb4 = (const float4*)(x + (((long)b*Nq + j)*Nq + i)*Lq);
    const ulonglong2* w12v = ((const ulonglong2*)s_w12) + fh*12;
    const ulonglong2* w11v = ((const ulonglong2*)s_w11) + fh*12;

    unsigned long long acc[24];
    #pragma unroll
    for (int q = 0; q < 24; q++) acc[q] = 0ull;

    for (int l4 = 0; l4 < 12; l4++) {
        float4 av = xa4[l4];
        float4 bv = xb4[l4];
        #pragma unroll
        for (int k = 0; k < 4; k++) {
            int l = l4*4 + k;
            float afl = (k==0) ? av.x : (k==1) ? av.y : (k==2) ? av.z : av.w;
            float bfl = (k==0) ? bv.x : (k==1) ? bv.y : (k==2) ? bv.z : bv.w;
            unsigned long long xa2 = pack2(afl);
            unsigned long long xb2 = pack2(bfl);
            const ulonglong2* wa = w12v + l*24;
            const ulonglong2* wb = w11v + l*24;
            #pragma unroll
            for (int q = 0; q < 12; q++) {
                ulonglong2 va = wa[q];
                acc[2*q]   = ffma2(xa2, va.x, acc[2*q]);
                acc[2*q+1] = ffma2(xa2, va.y, acc[2*q+1]);
            }
            #pragma unroll
            for (int q = 0; q < 12; q++) {
                ulonglong2 vb = wb[q];
                acc[2*q]   = ffma2(xb2, vb.x, acc[2*q]);
                acc[2*q+1] = ffma2(xb2, vb.y, acc[2*q+1]);
            }
        }
    }

    int f0 = fh * 48;
    const float4* bj4 = (const float4*)(g_bj + (b*Nq + j)*Fq + f0);
    float* orow = out + ((((long)b*Nq + i)*Nq + j)*Fq) + f0;
    bool isd = (i == j);
    #pragma unroll
    for (int q = 0; q < 12; q++) {
        float2 a  = *(float2*)(&acc[2*q]);
        float2 bb = *(float2*)(&acc[2*q+1]);
        float4 bjv = bj4[q];
        int f = 4*q;
        float4 o;
        o.x = a.x  + s_bi[f0+f]   + bjv.x;
        o.y = a.y  + s_bi[f0+f+1] + bjv.y;
        o.z = bb.x + s_bi[f0+f+2] + bjv.z;
        o.w = bb.y + s_bi[f0+f+3] + bjv.w;
        if (isd) {
            o.x += s_dg[f0+f];   o.y += s_dg[f0+f+1];
            o.z += s_dg[f0+f+2]; o.w += s_dg[f0+f+3];
        }
        *(float4*)(orow + f) = o;
    }
#endif // !HAS_TCGEN05
}

// ---------------- host: tensor maps + launch ----------------
typedef CUresult (*tmap_enc_fn)(CUtensorMap*, CUtensorMapDataType, cuuint32_t, void*,
                                const cuuint64_t*, const cuuint64_t*,
                                const cuuint32_t*, const cuuint32_t*,
                                CUtensorMapInterleave, CUtensorMapSwizzle,
                                CUtensorMapL2promotion, CUtensorMapFloatOOBfill);

static void build_maps(const float* x, CUtensorMap* mS, CUtensorMap* mT) {
    tmap_enc_fn enc = nullptr;
    cudaDriverEntryPointQueryResult qr;
    cudaGetDriverEntryPoint("cuTensorMapEncodeTiled", (void**)&enc, cudaEnableDefault, &qr);
    if (!enc) return;
    cuuint64_t dims[4]  = {48, 256, 256, 8};
    cuuint32_t box[4]   = {32, 128, 1, 1};
    cuuint32_t estr[4]  = {1, 1, 1, 1};
    // mapS: As rows = j (stride 192B), then i (49152B), b
    cuuint64_t strS[3]  = {192, 49152, 12582912};
    enc(mS, CU_TENSOR_MAP_DATA_TYPE_FLOAT32, 4, (void*)x, dims, strS, box, estr,
        CU_TENSOR_MAP_INTERLEAVE_NONE, CU_TENSOR_MAP_SWIZZLE_128B,
        CU_TENSOR_MAP_L2_PROMOTION_L2_128B, CU_TENSOR_MAP_FLOAT_OOB_FILL_NONE);
    // mapT: At rows = j at stride 49152B, then i (192B), b
    cuuint64_t strT[3]  = {49152, 192, 12582912};
    enc(mT, CU_TENSOR_MAP_DATA_TYPE_FLOAT32, 4, (void*)x, dims, strT, box, estr,
        CU_TENSOR_MAP_INTERLEAVE_NONE, CU_TENSOR_MAP_SWIZZLE_128B,
        CU_TENSOR_MAP_L2_PROMOTION_L2_128B, CU_TENSOR_MAP_FLOAT_OOB_FILL_NONE);
}

extern "C" void kernel_launch(void* const* d_in, const int* in_sizes, int n_in,
                              void* d_out, int out_size) {
    const float* x = (const float*)d_in[0];
    const float* w = (const float*)d_in[1];
    if (n_in >= 2 && in_sizes[0] == 15*Lq*Fq) {
        x = (const float*)d_in[1];
        w = (const float*)d_in[0];
    }
    float* out = (float*)d_out;

    cudaFuncSetAttribute(k_mma, cudaFuncAttributeMaxDynamicSharedMemorySize, SMEM_TOT);

    CUtensorMap mS, mT;
    build_maps(x, &mS, &mT);

    k_rowsum<<<Bq*Nq, 384>>>(x);
    k_colsum<<<Bq*32, 384>>>(x);
    k_trace<<<Bq, 2*Lq>>>(w);
    k_small<<<256, 192>>>(w);
    k_mma<<<128, 256, SMEM_TOT>>>(mS, mT, x, w, out);   // work iff tcgen05 available
    k_main_fb<<<Bq*Nq, 512>>>(x, w, out);               // work iff NOT available
}

// round 12
// speedup vs baseline: 1.9092x; 1.1508x over previous
#include <cuda_runtime.h>
#include <cuda.h>
#include <cstdint>

#define Bq 8
#define Nq 256
#define Lq 48
#define Fq 96
#define LF (Lq*Fq)

#if defined(__CUDA_ARCH__) && (__CUDA_ARCH__ == 1030) && \
    (defined(__CUDA_ARCH_FEAT_SM103_ALL) || defined(__CUDA_ARCH_SPECIFIC__) || defined(__CUDA_ARCH_FAMILY_SPECIFIC__))
#define HAS_TCGEN05 1
#else
#define HAS_TCGEN05 0
#endif

// ---------------- scratch ----------------
__device__ __align__(16) float g_rowsum[Bq*Nq*Lq];
__device__ __align__(16) float g_colsum[Bq*Nq*Lq];
__device__ __align__(16) float g_diag[Bq*Nq*Lq];
__device__ __align__(16) float g_dgc[Bq*Fq];
__device__ __align__(16) float g_bic[Bq*Fq];
__device__ __align__(16) float g_bi[Bq*Nq*Fq];
__device__ __align__(16) float g_bj[Bq*Nq*Fq];
__device__ __align__(16) float g_dg[Bq*Nq*Fq];

// ---------------- generic helpers ----------------
__device__ __forceinline__ unsigned long long ffma2(unsigned long long a,
                                                    unsigned long long b,
                                                    unsigned long long c) {
    unsigned long long d;
    asm("fma.rn.f32x2 %0, %1, %2, %3;" : "=l"(d) : "l"(a), "l"(b), "l"(c));
    return d;
}
__device__ __forceinline__ unsigned long long pack2(float v) {
    unsigned long long r;
    asm("mov.b64 %0, {%1, %1};" : "=l"(r) : "f"(v));
    return r;
}

// ---------------- pass 1a: rowsum + diag ----------------
__global__ void k_rowsum(const float* __restrict__ x) {
    int blk = blockIdx.x; int b = blk >> 8, i = blk & 255;
    int tid = threadIdx.x;               // 384
    int l = tid % Lq, ys = tid / Lq;
    const float* base = x + (((long)b*Nq + i) * Nq) * Lq;
    float acc = 0.f;
    #pragma unroll 4
    for (int s = 0; s < 32; s++) acc += base[(ys*32 + s)*Lq + l];
    __shared__ float sp[8][Lq];
    sp[ys][l] = acc;
    __syncthreads();
    if (tid < Lq) {
        float r = 0.f;
        #pragma unroll
        for (int y = 0; y < 8; y++) r += sp[y][tid];
        g_rowsum[(b*Nq + i)*Lq + tid] = r;
        g_diag[(b*Nq + i)*Lq + tid]   = base[i*Lq + tid];
    }
}

// ---------------- pass 1b: colsum ----------------
__global__ void k_colsum(const float* __restrict__ x) {
    int blk = blockIdx.x; int b = blk >> 5, jt = blk & 31;
    int tid = threadIdx.x;               // 384
    int l = tid % Lq, y = tid / Lq;
    int j = jt * 8 + y;
    const float* base = x + ((long)b*Nq*Nq + (long)j) * Lq + l;
    float acc = 0.f;
    #pragma unroll 8
    for (int i = 0; i < Nq; i++) acc += base[(long)i * Nq * Lq];
    g_colsum[(b*Nq + j)*Lq + l] = acc;
}

// ---------------- pass 1c: trace/totsum -> per-b F constants ----------------
__global__ void k_trace(const float* __restrict__ w) {
    int b = blockIdx.x; int t = threadIdx.x;   // 96 threads
    __shared__ float s_tr[Lq], s_ts[Lq];
    if (t < Lq) {
        float a = 0.f;
        #pragma unroll 8
        for (int i = 0; i < Nq; i++) a += g_diag[(b*Nq + i)*Lq + t];
        s_tr[t] = a;
    } else {
        int l = t - Lq;
        float a = 0.f;
        #pragma unroll 8
        for (int i = 0; i < Nq; i++) a += g_rowsum[(b*Nq + i)*Lq + l];
        s_ts[l] = a;
    }
    __syncthreads();
    float dgc = 0.f, bic = 0.f;
    #pragma unroll 4
    for (int l = 0; l < Lq; l++) {
        float tr = s_tr[l], ts = s_ts[l];
        dgc += tr * w[3*LF  + l*Fq + t] + ts * w[4*LF  + l*Fq + t];
        bic += tr * w[13*LF + l*Fq + t] + ts * w[14*LF + l*Fq + t];
    }
    g_dgc[b*Fq + t] = dgc;
    g_bic[b*Fq + t] = bic;
}

// ---------------- pass 2: small GEMMs -> bi/bj/dg ----------------
__global__ void __launch_bounds__(192) k_small(const float* __restrict__ w) {
    __shared__ float sd[8][Lq], sr[8][Lq], sc[8][Lq];
    int row0 = blockIdx.x * 8;
    int tid = threadIdx.x;               // 192 = 24 fx * 8 y
    for (int idx = tid; idx < 8*Lq; idx += 192) {
        int r = idx / Lq, l = idx % Lq;
        sd[r][l] = g_diag  [(row0 + r)*Lq + l];
        sr[r][l] = g_rowsum[(row0 + r)*Lq + l];
        sc[r][l] = g_colsum[(row0 + r)*Lq + l];
    }
    __syncthreads();
    int fx = tid % 24, y = tid / 24;
    int row = row0 + y; int b = row >> 8;
    float4 dg = {0,0,0,0}, bj = {0,0,0,0}, bi = {0,0,0,0};
    const float4* w4 = (const float4*)w;
    #pragma unroll 4
    for (int l = 0; l < Lq; l++) {
        float dv = sd[y][l], rv = sr[y][l], cv = sc[y][l];
        int base = (l*Fq)/4 + fx;
        float4 w0 = w4[base + (0*LF)/4],  w1 = w4[base + (1*LF)/4],  w2 = w4[base + (2*LF)/4];
        float4 w5 = w4[base + (5*LF)/4],  w6 = w4[base + (6*LF)/4],  w7 = w4[base + (7*LF)/4];
        float4 w8 = w4[base + (8*LF)/4],  w9 = w4[base + (9*LF)/4],  wA = w4[base + (10*LF)/4];
        dg.x += dv*w0.x + rv*w1.x + cv*w2.x;  dg.y += dv*w0.y + rv*w1.y + cv*w2.y;
        dg.z += dv*w0.z + rv*w1.z + cv*w2.z;  dg.w += dv*w0.w + rv*w1.w + cv*w2.w;
        bj.x += dv*w5.x + rv*w6.x + cv*w7.x;  bj.y += dv*w5.y + rv*w6.y + cv*w7.y;
        bj.z += dv*w5.z + rv*w6.z + cv*w7.z;  bj.w += dv*w5.w + rv*w6.w + cv*w7.w;
        bi.x += dv*w8.x + rv*w9.x + cv*wA.x;  bi.y += dv*w8.y + rv*w9.y + cv*wA.y;
        bi.z += dv*w8.z + rv*w9.z + cv*wA.z;  bi.w += dv*w8.w + rv*w9.w + cv*wA.w;
    }
    int f = fx * 4;
    const float4 dgc = *(const float4*)(g_dgc + b*Fq + f);
    const float4 bic = *(const float4*)(g_bic + b*Fq + f);
    dg.x += dgc.x; dg.y += dgc.y; dg.z += dgc.z; dg.w += dgc.w;
    bi.x += bic.x; bi.y += bic.y; bi.z += bic.z; bi.w += bic.w;
    *(float4*)(g_dg + row*Fq + f) = dg;
    *(float4*)(g_bj + row*Fq + f) = bj;
    *(float4*)(g_bi + row*Fq + f) = bi;
}

// ============================================================================
// tcgen05 path: TMA(SW128) staging of raw fp32, tf32 MMA, pipelined,
// SMEM-transposed coalesced epilogue
// ============================================================================
#if HAS_TCGEN05
__device__ __forceinline__ uint32_t smem_u32(const void* p) {
    uint32_t a;
    asm("{ .reg .u64 t; cvta.to.shared.u64 t, %1; cvt.u32.u64 %0, t; }" : "=r"(a) : "l"(p));
    return a;
}
__device__ __forceinline__ float tf32_rna(float x) {
    uint32_t r;
    asm("cvt.rna.tf32.f32 %0, %1;" : "=r"(r) : "f"(x));
    return __uint_as_float(r);
}
__device__ __forceinline__ void mma_tf32_ss(uint32_t d, uint64_t ad, uint64_t bd,
                                            uint32_t idesc, uint32_t en) {
    asm volatile(
        "{\n\t.reg .pred p;\n\tsetp.ne.u32 p, %4, 0;\n\t"
        "tcgen05.mma.cta_group::1.kind::tf32 [%0], %1, %2, %3, {%5, %5, %5, %5}, p;\n\t}"
        :: "r"(d), "l"(ad), "l"(bd), "r"(idesc), "r"(en), "r"(0u) : "memory");
}
#define TMA4(dst, map, c0, c1, c2, c3, mb) \
    asm volatile("cp.async.bulk.tensor.4d.shared::cta.global.tile.mbarrier::complete_tx::bytes " \
        "[%0], [%1, {%2, %3, %4, %5}], [%6];" \
        :: "r"(dst), "l"(map), "r"(c0), "r"(c1), "r"(c2), "r"(c3), "r"(mb) : "memory")
#define TC_ALLOC(sm, n)   asm volatile("tcgen05.alloc.cta_group::1.sync.aligned.shared::cta.b32 [%0], %1;" :: "r"(sm), "r"(n) : "memory")
#define TC_DEALLOC(t, n)  asm volatile("tcgen05.dealloc.cta_group::1.sync.aligned.b32 %0, %1;" :: "r"(t), "r"(n))
#define TC_RELINQ()       asm volatile("tcgen05.relinquish_alloc_permit.cta_group::1.sync.aligned;")
#define TC_COMMIT(mb)     asm volatile("tcgen05.commit.cta_group::1.mbarrier::arrive::one.shared::cluster.b64 [%0];" :: "r"(mb) : "memory")
#define TC_WAIT_LD()      asm volatile("tcgen05.wait::ld.sync.aligned;" ::: "memory")
#define TC_FENCE_BEFORE() asm volatile("tcgen05.fence::before_thread_sync;" ::: "memory")
#define TC_FENCE_AFTER()  asm volatile("tcgen05.fence::after_thread_sync;" ::: "memory")
#define FENCE_ASYNC()     asm volatile("fence.proxy.async.shared::cta;" ::: "memory")
#define MBAR_INIT(mb, c)  asm volatile("mbarrier.init.shared.b64 [%0], %1;" :: "r"(mb), "r"(c) : "memory")
#define MBAR_INVAL(mb)    asm volatile("mbarrier.inval.shared.b64 [%0];" :: "r"(mb) : "memory")
#define MBAR_EXPECT(mb, n) asm volatile("mbarrier.arrive.expect_tx.shared.b64 _, [%0], %1;" :: "r"(mb), "r"(n) : "memory")
__device__ __forceinline__ void mbar_wait(uint32_t mb, uint32_t ph) {
    uint32_t done;
    asm volatile(
        "{\n\t.reg .pred p;\n\t"
        "mbarrier.try_wait.parity.acquire.cta.shared::cta.b64 p, [%1], %2;\n\t"
        "selp.b32 %0, 1, 0, p;\n\t}"
        : "=r"(done) : "r"(mb), "r"(ph) : "memory");
    if (!done) {
        asm volatile(
            "{\n\t.reg .pred P1;\n\t"
            "WL_%=:\n\t"
            "mbarrier.try_wait.parity.acquire.cta.shared::cta.b64 P1, [%0], %1, 0x989680;\n\t"
            "@P1 bra.uni WD_%=;\n\t"
            "bra.uni WL_%=;\n\t"
            "WD_%=:\n\t}"
            :: "r"(mb), "r"(ph) : "memory");
    }
}
#define LDTM_X32(r, a) \
    asm volatile("tcgen05.ld.sync.aligned.32x32b.x32.b32 " \
        "{%0, %1, %2, %3, %4, %5, %6, %7, %8, %9, %10, %11, %12, %13, %14, %15, " \
        " %16, %17, %18, %19, %20, %21, %22, %23, %24, %25, %26, %27, %28, %29, %30, %31}, [%32];" \
        : "=r"((r)[0]),  "=r"((r)[1]),  "=r"((r)[2]),  "=r"((r)[3]), \
          "=r"((r)[4]),  "=r"((r)[5]),  "=r"((r)[6]),  "=r"((r)[7]), \
          "=r"((r)[8]),  "=r"((r)[9]),  "=r"((r)[10]), "=r"((r)[11]), \
          "=r"((r)[12]), "=r"((r)[13]), "=r"((r)[14]), "=r"((r)[15]), \
          "=r"((r)[16]), "=r"((r)[17]), "=r"((r)[18]), "=r"((r)[19]), \
          "=r"((r)[20]), "=r"((r)[21]), "=r"((r)[22]), "=r"((r)[23]), \
          "=r"((r)[24]), "=r"((r)[25]), "=r"((r)[26]), "=r"((r)[27]), \
          "=r"((r)[28]), "=r"((r)[29]), "=r"((r)[30]), "=r"((r)[31]) \
        : "r"(a))
#define LDTM_X16(r, a) \
    asm volatile("tcgen05.ld.sync.aligned.32x32b.x16.b32 " \
        "{%0, %1, %2, %3, %4, %5, %6, %7, %8, %9, %10, %11, %12, %13, %14, %15}, [%16];" \
        : "=r"((r)[0]),  "=r"((r)[1]),  "=r"((r)[2]),  "=r"((r)[3]), \
          "=r"((r)[4]),  "=r"((r)[5]),  "=r"((r)[6]),  "=r"((r)[7]), \
          "=r"((r)[8]),  "=r"((r)[9]),  "=r"((r)[10]), "=r"((r)[11]), \
          "=r"((r)[12]), "=r"((r)[13]), "=r"((r)[14]), "=r"((r)[15]) \
        : "r"(a))

// K-major SW128 descriptors: LBO=1, SBO=64
static constexpr uint64_t DESC_SW128 =
    (uint64_t(2) << 61) | (uint64_t(1) << 46) | (uint64_t(64) << 32) | (uint64_t(1) << 16);
#define MK_DESC(addr) (DESC_SW128 | ((uint64_t)((addr) >> 4) & 0x3FFF))
#define IDESC_TF32 ((1u<<4) | (2u<<7) | (2u<<10) | (12u<<17) | (8u<<24))

__device__ __forceinline__ uint32_t b_off(int n, int k) {
    uint32_t o = ((k >> 5) * 12288u) + (uint32_t)n * 128u + ((k & 31) << 2);
    return o ^ ((o >> 3) & 0x70u);
}
#endif // HAS_TCGEN05

// SMEM layout
#define A_TILE_SZ 32768               // two 16KB SW128 k-blocks
#define OFF_TMEM  0
#define OFF_MBAR  16                  // 4 mbars: tma0, tma1, mma0, mma1
#define OFF_B12   1024
#define OFF_B11   (OFF_B12 + 24576)
#define OFF_A     (OFF_B11 + 24576)   // 4 tiles: As0, At0, As1, At1
#define OFF_STG   (OFF_A + 4*A_TILE_SZ)   // 181248
#define STG_PITCH 52                  // floats; 208B rows -> conflict-free STS.128
#define SMEM_TOT  (OFF_STG + 128*STG_PITCH*4 + 16)   // 207888

#if HAS_TCGEN05
__device__ __forceinline__ void issue_group(uint32_t tmem_d, uint64_t dAs, uint64_t dAt,
                                            uint64_t dB12, uint64_t dB11, uint32_t mb) {
    const uint64_t acd[6] = {0, 2, 4, 6, 1024 + 4, 1024 + 6};
    const uint64_t bcd[6] = {0, 2, 4, 6, 768 + 0, 768 + 2};
    uint32_t en = 0;
    #pragma unroll
    for (int c = 0; c < 6; c++) { mma_tf32_ss(tmem_d, dAs + acd[c], dB12 + bcd[c], IDESC_TF32, en); en = 1; }
    #pragma unroll
    for (int c = 0; c < 6; c++)   mma_tf32_ss(tmem_d, dAt + acd[c], dB11 + bcd[c], IDESC_TF32, 1);
    TC_COMMIT(mb);
}

__device__ __forceinline__ void issue_stage(uint32_t smb, const CUtensorMap* mapS,
                                            const CUtensorMap* mapT,
                                            int b, int ii, int j0, int s) {
    uint32_t mb = smb + OFF_MBAR + s*8;
    MBAR_EXPECT(mb, 4*16384);
    uint32_t as = smb + OFF_A + (2*s + 0)*A_TILE_SZ;
    uint32_t at = smb + OFF_A + (2*s + 1)*A_TILE_SZ;
    TMA4(as,         mapS, 0,  j0, ii, b, mb);
    TMA4(as + 16384, mapS, 16, j0, ii, b, mb);
    TMA4(at,         mapT, 0,  j0, ii, b, mb);
    TMA4(at + 16384, mapT, 16, j0, ii, b, mb);
}
#endif

// grid 128: b = blk>>4, jt = (blk>>3)&1, ic = blk&7; 32 i-iters per block.
__global__ void __launch_bounds__(256, 1) k_mma(const __grid_constant__ CUtensorMap mapS,
                                                const __grid_constant__ CUtensorMap mapT,
                                                const float* __restrict__ x,
                                                const float* __restrict__ w,
                                                float* __restrict__ out) {
#if HAS_TCGEN05
    extern __shared__ char sm[];
    uint32_t smb = smem_u32(sm);
    int tid = threadIdx.x;
    int wid = tid >> 5, lane = tid & 31;

    int blk = blockIdx.x;
    int b = blk >> 4, jt = (blk >> 3) & 1, ic = blk & 7;
    int j0 = jt * 128;

    if (wid == 0) TC_ALLOC(smb + OFF_TMEM, 256);
    __syncthreads();
    uint32_t tmem;
    asm volatile("ld.shared.b32 %0, [%1];" : "=r"(tmem) : "r"(smb + OFF_TMEM));

    if (tid == 0) {
        MBAR_INIT(smb + OFF_MBAR + 0,  1);   // tma_full[0]
        MBAR_INIT(smb + OFF_MBAR + 8,  1);   // tma_full[1]
        MBAR_INIT(smb + OFF_MBAR + 16, 1);   // mma_done[0]
        MBAR_INIT(smb + OFF_MBAR + 24, 1);   // mma_done[1]
    }

    // B tiles (K-major SW128), tf32-rounded via registers
    for (int idx = tid; idx < Lq*Fq; idx += 256) {
        int f = idx / Lq, l = idx % Lq;
        *(float*)(sm + OFF_B12 + b_off(f, l)) = tf32_rna(w[12*LF + l*Fq + f]);
        *(float*)(sm + OFF_B11 + b_off(f, l)) = tf32_rna(w[11*LF + l*Fq + f]);
    }
    FENCE_ASYNC();
    __syncthreads();

    uint64_t dAs[2] = {MK_DESC(smb + OFF_A + 0*A_TILE_SZ), MK_DESC(smb + OFF_A + 2*A_TILE_SZ)};
    uint64_t dAt[2] = {MK_DESC(smb + OFF_A + 1*A_TILE_SZ), MK_DESC(smb + OFF_A + 3*A_TILE_SZ)};
    uint64_t dB12 = MK_DESC(smb + OFF_B12);
    uint64_t dB11 = MK_DESC(smb + OFF_B11);

    uint32_t tph[2] = {0, 0}, mph[2] = {0, 0};

    // prologue: stage 0 and 1; MMA(0)
    if (tid == 0) {
        issue_stage(smb, &mapS, &mapT, b, ic*32 + 0, j0, 0);
        issue_stage(smb, &mapS, &mapT, b, ic*32 + 1, j0, 1);
        mbar_wait(smb + OFF_MBAR + 0, 0);
        issue_group(tmem, dAs[0], dAt[0], dB12, dB11, smb + OFF_MBAR + 16);
    }
    tph[0] = 1;

    int h = wid >> 2, sub = wid & 3;
    float* stg = (float*)(sm + OFF_STG);

    for (int it = 0; it < 32; it++) {
        int i = ic*32 + it;
        int cur = it & 1, nxt = cur ^ 1;

        // tid0: issue MMA(it+1) into D[nxt] once its stage is full
        if (tid == 0 && it + 1 < 32) {
            mbar_wait(smb + OFF_MBAR + nxt*8, tph[nxt]);
            issue_group(tmem + nxt*128, dAs[nxt], dAt[nxt], dB12, dB11,
                        smb + OFF_MBAR + 16 + nxt*8);
        }
        if (it + 1 < 32) tph[nxt] ^= 1;

        // all: wait MMA(it) done
        mbar_wait(smb + OFF_MBAR + 16 + cur*8, mph[cur]);
        mph[cur] ^= 1;
        TC_FENCE_AFTER();

        // tid0: refill smem buffer cur for iteration it+2 (A[cur] free now)
        if (tid == 0 && it + 2 < 32)
            issue_stage(smb, &mapS, &mapT, b, ic*32 + it + 2, j0, cur);

        // all 8 warps: read D[cur] (cols half h, rows = subpartition sub)
        uint32_t d[48];
        uint32_t td = tmem + cur*128 + h*48;
        LDTM_X32(d, td);
        LDTM_X16(d + 32, td + 32);
        TC_WAIT_LD();
        TC_FENCE_BEFORE();
        __syncthreads();           // D[cur] reads drained before MMA(it+2) issue

        // ---- SMEM-transposed coalesced epilogue, two f-halves ----
        int irow = i - j0;         // diag row within this j tile (may be out of range)
        long obase = (((long)b*Nq + i)*Nq + j0)*Fq;
        #pragma unroll
        for (int ph = 0; ph < 2; ph++) {
            if (h == ph) {
                int row = sub*32 + lane;
                #pragma unroll
                for (int q = 0; q < 12; q++)
                    *(float4*)(stg + row*STG_PITCH + q*4) = *(float4*)(&d[q*4]);
            }
            __syncthreads();
            const float* bjb = g_bj + ((long)b*Nq + j0)*Fq + ph*48;
            const float* bib = g_bi + ((long)b*Nq + i)*Fq + ph*48;
            const float* dgb = g_dg + ((long)b*Nq + i)*Fq + ph*48;
            #pragma unroll
            for (int q = 0; q < 6; q++) {
                int p = tid + 256*q;
                int row = p / 12, c = p % 12;
                float4 v  = *(float4*)(stg + row*STG_PITCH + c*4);
                float4 bj = *(const float4*)(bjb + (long)row*Fq + c*4);
                float4 bi = *(const float4*)(bib + c*4);
                v.x += bj.x + bi.x;  v.y += bj.y + bi.y;
                v.z += bj.z + bi.z;  v.w += bj.w + bi.w;
                if (row == irow) {
                    float4 gv = *(const float4*)(dgb + c*4);
                    v.x += gv.x; v.y += gv.y; v.z += gv.z; v.w += gv.w;
                }
                *(float4*)(out + obase + (long)row*Fq + ph*48 + c*4) = v;
            }
            __syncthreads();
        }
    }

    if (tid == 0) {
        MBAR_INVAL(smb + OFF_MBAR + 0);  MBAR_INVAL(smb + OFF_MBAR + 8);
        MBAR_INVAL(smb + OFF_MBAR + 16); MBAR_INVAL(smb + OFF_MBAR + 24);
    }
    __syncthreads();
    if (wid == 0) {
        TC_RELINQ();
        TC_DEALLOC(tmem, 256);
    }
#endif // HAS_TCGEN05
}

// ============================================================================
// CUDA-core fallback dense kernel (active only when tcgen05 is unavailable)
// ============================================================================
__global__ void __launch_bounds__(512) k_main_fb(const float* __restrict__ x,
                                                 const float* __restrict__ w,
                                                 float* __restrict__ out) {
#if !HAS_TCGEN05
    __shared__ __align__(16) float s_w12[LF];
    __shared__ __align__(16) float s_w11[LF];
    __shared__ __align__(16) float s_bi[Fq];
    __shared__ __align__(16) float s_dg[Fq];

    int blk = blockIdx.x; int b = blk >> 8, i = blk & 255;
    int tid = threadIdx.x;
    int j = tid >> 1, fh = tid & 1;

    for (int t = tid; t < LF; t += 512) {
        s_w11[t] = w[11*LF + t];
        s_w12[t] = w[12*LF + t];
    }
    {
        int rb = (b*Nq + i)*Fq;
        if (tid < Fq)            s_bi[tid]        = g_bi[rb + tid];
        else if (tid < 2*Fq)     s_dg[tid - Fq]   = g_dg[rb + tid - Fq];
    }
    __syncthreads();

    const float4* xa4 = (const float4*)(x + (((long)b*Nq + i)*Nq + j)*Lq);
    const float4* xb4 = (const float4*)(x + (((long)b*Nq + j)*Nq + i)*Lq);
    const ulonglong2* w12v = ((const ulonglong2*)s_w12) + fh*12;
    const ulonglong2* w11v = ((const ulonglong2*)s_w11) + fh*12;

    unsigned long long acc[24];
    #pragma unroll
    for (int q = 0; q < 24; q++) acc[q] = 0ull;

    for (int l4 = 0; l4 < 12; l4++) {
        float4 av = xa4[l4];
        float4 bv = xb4[l4];
        #pragma unroll
        for (int k = 0; k < 4; k++) {
            int l = l4*4 + k;
            float afl = (k==0) ? av.x : (k==1) ? av.y : (k==2) ? av.z : av.w;
            float bfl = (k==0) ? bv.x : (k==1) ? bv.y : (k==2) ? bv.z : bv.w;
            unsigned long long xa2 = pack2(afl);
            unsigned long long xb2 = pack2(bfl);
            const ulonglong2* wa = w12v + l*24;
            const ulonglong2* wb = w11v + l*24;
            #pragma unroll
            for (int q = 0; q < 12; q++) {
                ulonglong2 va = wa[q];
                acc[2*q]   = ffma2(xa2, va.x, acc[2*q]);
                acc[2*q+1] = ffma2(xa2, va.y, acc[2*q+1]);
            }
            #pragma unroll
            for (int q = 0; q < 12; q++) {
                ulonglong2 vb = wb[q];
                acc[2*q]   = ffma2(xb2, vb.x, acc[2*q]);
                acc[2*q+1] = ffma2(xb2, vb.y, acc[2*q+1]);
            }
        }
    }

    int f0 = fh * 48;
    const float4* bj4 = (const float4*)(g_bj + (b*Nq + j)*Fq + f0);
    float* orow = out + ((((long)b*Nq + i)*Nq + j)*Fq) + f0;
    bool isd = (i == j);
    #pragma unroll
    for (int q = 0; q < 12; q++) {
        float2 a  = *(float2*)(&acc[2*q]);
        float2 bb = *(float2*)(&acc[2*q+1]);
        float4 bjv = bj4[q];
        int f = 4*q;
        float4 o;
        o.x = a.x  + s_bi[f0+f]   + bjv.x;
        o.y = a.y  + s_bi[f0+f+1] + bjv.y;
        o.z = bb.x + s_bi[f0+f+2] + bjv.z;
        o.w = bb.y + s_bi[f0+f+3] + bjv.w;
        if (isd) {
            o.x += s_dg[f0+f];   o.y += s_dg[f0+f+1];
            o.z += s_dg[f0+f+2]; o.w += s_dg[f0+f+3];
        }
        *(float4*)(orow + f) = o;
    }
#endif // !HAS_TCGEN05
}

// ---------------- host: tensor maps + launch ----------------
typedef CUresult (*tmap_enc_fn)(CUtensorMap*, CUtensorMapDataType, cuuint32_t, void*,
                                const cuuint64_t*, const cuuint64_t*,
                                const cuuint32_t*, const cuuint32_t*,
                                CUtensorMapInterleave, CUtensorMapSwizzle,
                                CUtensorMapL2promotion, CUtensorMapFloatOOBfill);

static void build_maps(const float* x, CUtensorMap* mS, CUtensorMap* mT) {
    tmap_enc_fn enc = nullptr;
    cudaDriverEntryPointQueryResult qr;
    cudaGetDriverEntryPoint("cuTensorMapEncodeTiled", (void**)&enc, cudaEnableDefault, &qr);
    if (!enc) return;
    cuuint64_t dims[4]  = {48, 256, 256, 8};
    cuuint32_t box[4]   = {32, 128, 1, 1};
    cuuint32_t estr[4]  = {1, 1, 1, 1};
    cuuint64_t strS[3]  = {192, 49152, 12582912};
    enc(mS, CU_TENSOR_MAP_DATA_TYPE_FLOAT32, 4, (void*)x, dims, strS, box, estr,
        CU_TENSOR_MAP_INTERLEAVE_NONE, CU_TENSOR_MAP_SWIZZLE_128B,
        CU_TENSOR_MAP_L2_PROMOTION_L2_128B, CU_TENSOR_MAP_FLOAT_OOB_FILL_NONE);
    cuuint64_t strT[3]  = {49152, 192, 12582912};
    enc(mT, CU_TENSOR_MAP_DATA_TYPE_FLOAT32, 4, (void*)x, dims, strT, box, estr,
        CU_TENSOR_MAP_INTERLEAVE_NONE, CU_TENSOR_MAP_SWIZZLE_128B,
        CU_TENSOR_MAP_L2_PROMOTION_L2_128B, CU_TENSOR_MAP_FLOAT_OOB_FILL_NONE);
}

extern "C" void kernel_launch(void* const* d_in, const int* in_sizes, int n_in,
                              void* d_out, int out_size) {
    const float* x = (const float*)d_in[0];
    const float* w = (const float*)d_in[1];
    if (n_in >= 2 && in_sizes[0] == 15*Lq*Fq) {
        x = (const float*)d_in[1];
        w = (const float*)d_in[0];
    }
    float* out = (float*)d_out;

    cudaFuncSetAttribute(k_mma, cudaFuncAttributeMaxDynamicSharedMemorySize, SMEM_TOT);

    CUtensorMap mS, mT;
    build_maps(x, &mS, &mT);

    k_rowsum<<<Bq*Nq, 384>>>(x);
    k_colsum<<<Bq*32, 384>>>(x);
    k_trace<<<Bq, 2*Lq>>>(w);
    k_small<<<256, 192>>>(w);
    k_mma<<<128, 256, SMEM_TOT>>>(mS, mT, x, w, out);   // work iff tcgen05 available
    k_main_fb<<<Bq*Nq, 512>>>(x, w, out);               // work iff NOT available
}